// round 13
// baseline (speedup 1.0000x reference)
#include <cuda_runtime.h>

// Problem constants
#define BB 2
#define SS 4096
#define DD 512
#define HH 8
#define DK 64
#define MM (BB * SS)   // 8192 rows
#define QT 128         // q rows per attention block
#define KT 64          // k cols per attention tile

// ---------------------------------------------------------------------------
// Scratch (device globals — no runtime allocation)
// g_Qt / g_Kt are TRANSPOSED per head: [b][h][dk][s]  (dk-major)
// g_V natural: [b][h][s][dk]
// ---------------------------------------------------------------------------
__device__ __align__(16) float g_Qt[BB * HH * DK * SS];
__device__ __align__(16) float g_Kt[BB * HH * DK * SS];
__device__ __align__(16) float g_V [BB * HH * SS * DK];
__device__ __align__(16) float g_att[BB * SS * DD];       // [B,S,D]

// ---------------------------------------------------------------------------
// Packed fp32x2 helpers
// ---------------------------------------------------------------------------
typedef unsigned long long u64;

__device__ __forceinline__ u64 ffma2(u64 a, u64 b, u64 c) {
    u64 d;
    asm("fma.rn.f32x2 %0, %1, %2, %3;" : "=l"(d) : "l"(a), "l"(b), "l"(c));
    return d;
}
__device__ __forceinline__ u64 fmul2(u64 a, u64 b) {
    u64 d;
    asm("mul.rn.f32x2 %0, %1, %2;" : "=l"(d) : "l"(a), "l"(b));
    return d;
}
__device__ __forceinline__ u64 pack2(float x) {
    u64 d;
    asm("mov.b64 %0, {%1, %1};" : "=l"(d) : "f"(x));
    return d;
}
__device__ __forceinline__ u64 packpair(float a, float b) {
    u64 d;
    asm("mov.b64 %0, {%1, %2};" : "=l"(d) : "f"(a), "f"(b));
    return d;
}
__device__ __forceinline__ float2 unpack2(u64 v) {
    float2 r;
    asm("mov.b64 {%0, %1}, %2;" : "=f"(r.x), "=f"(r.y) : "l"(v));
    return r;
}

// ---------------------------------------------------------------------------
// Tiled SGEMM with bias (unchanged, proven):
//   C[i,j] = sum_k A[i,k] * W[j,k] + bias[j]
//   mode 0/1: write TRANSPOSED into g_Qt/g_Kt  ([b][h][dk][s])
//   mode 2  : write natural into g_V           ([b][h][s][dk])
//   mode 3  : A := g_att, plain row-major into Cout
// ---------------------------------------------------------------------------
__global__ __launch_bounds__(256)
void gemm_bias_kernel(const float* __restrict__ A,
                      const float* __restrict__ W,
                      const float* __restrict__ bias,
                      float* __restrict__ Cout,
                      int mode)
{
    __shared__ __align__(16) float As[16][64];
    __shared__ __align__(16) float Bs[16][128];

    const float* Ap = (mode == 3) ? g_att : A;

    const int tid = threadIdx.x;
    const int tx  = tid & 15;
    const int ty  = tid >> 4;
    const int bm  = blockIdx.y;
    const int bn  = blockIdx.x;

    const int lrow = tid >> 2;
    const int lk4  = (tid & 3) << 2;

    const float* Aptr  = Ap + (size_t)(bm * 64 + lrow) * DD + lk4;
    const float* Wptr0 = W  + (size_t)(bn * 128 + lrow) * DD + lk4;
    const float* Wptr1 = Wptr0 + (size_t)64 * DD;

    u64 c[16];
    #pragma unroll
    for (int i = 0; i < 16; i++) c[i] = 0ull;

    for (int kk = 0; kk < DD; kk += 16) {
        float4 a4 = *(const float4*)(Aptr  + kk);
        float4 w0 = *(const float4*)(Wptr0 + kk);
        float4 w1 = *(const float4*)(Wptr1 + kk);
        __syncthreads();
        As[lk4 + 0][lrow] = a4.x;  As[lk4 + 1][lrow] = a4.y;
        As[lk4 + 2][lrow] = a4.z;  As[lk4 + 3][lrow] = a4.w;
        Bs[lk4 + 0][lrow] = w0.x;  Bs[lk4 + 1][lrow] = w0.y;
        Bs[lk4 + 2][lrow] = w0.z;  Bs[lk4 + 3][lrow] = w0.w;
        Bs[lk4 + 0][lrow + 64] = w1.x;  Bs[lk4 + 1][lrow + 64] = w1.y;
        Bs[lk4 + 2][lrow + 64] = w1.z;  Bs[lk4 + 3][lrow + 64] = w1.w;
        __syncthreads();

        #pragma unroll
        for (int k = 0; k < 16; k++) {
            float4 av = *(const float4*)&As[k][ty << 2];
            const u64* bp = (const u64*)&Bs[k][tx << 3];
            u64 b0 = bp[0], b1 = bp[1], b2 = bp[2], b3 = bp[3];
            u64 ax = pack2(av.x), ay = pack2(av.y);
            u64 az = pack2(av.z), aw = pack2(av.w);
            c[0]  = ffma2(ax, b0, c[0]);  c[1]  = ffma2(ax, b1, c[1]);
            c[2]  = ffma2(ax, b2, c[2]);  c[3]  = ffma2(ax, b3, c[3]);
            c[4]  = ffma2(ay, b0, c[4]);  c[5]  = ffma2(ay, b1, c[5]);
            c[6]  = ffma2(ay, b2, c[6]);  c[7]  = ffma2(ay, b3, c[7]);
            c[8]  = ffma2(az, b0, c[8]);  c[9]  = ffma2(az, b1, c[9]);
            c[10] = ffma2(az, b2, c[10]); c[11] = ffma2(az, b3, c[11]);
            c[12] = ffma2(aw, b0, c[12]); c[13] = ffma2(aw, b1, c[13]);
            c[14] = ffma2(aw, b2, c[14]); c[15] = ffma2(aw, b3, c[15]);
        }
    }

    const int r0 = bm * 64 + (ty << 2);
    const int c0 = bn * 128 + (tx << 3);
    float* qkv = (mode == 0) ? g_Qt : (mode == 1) ? g_Kt : g_V;

    #pragma unroll
    for (int i = 0; i < 4; i++) {
        const int row = r0 + i;
        #pragma unroll
        for (int jp = 0; jp < 4; jp++) {
            float2 cv = unpack2(c[i * 4 + jp]);
            const int col0 = c0 + jp * 2;
            float v0 = cv.x + bias[col0];
            float v1 = cv.y + bias[col0 + 1];
            if (mode < 2) {
                const int b  = row >> 12;
                const int s  = row & 4095;
                const int h  = col0 >> 6;
                const int dk = col0 & 63;
                float* base = &qkv[((size_t)(b * HH + h) * DK + dk) * SS + s];
                base[0]  = v0;
                base[SS] = v1;
            } else if (mode == 2) {
                const int b  = row >> 12;
                const int s  = row & 4095;
                const int h  = col0 >> 6;
                const int dk = col0 & 63;
                float* dst = &qkv[(((size_t)(b * HH + h) << 12) + s) * DK + dk];
                dst[0] = v0;  dst[1] = v1;
            } else {
                float* dst = &Cout[(size_t)row * DD + col0];
                dst[0] = v0;  dst[1] = v1;
            }
        }
    }
}

// ---------------------------------------------------------------------------
// Register-tiled causal flash attention, 8x8 micro-tile, 3 CTAs/SM.
// Block 128 thr: tx 0..7 (8 keys / 8 dk-cols each), ty 0..15 (8 q rows each).
// P bounced through a 16-key chunk buffer (4 passes, same-warp sync only).
// Smem 72.5 KB -> 3 CTAs/SM for latency cover.
// ---------------------------------------------------------------------------
#define QS_STRIDE 128        // floats (row-contiguous access; no pad needed)
#define KS_STRIDE 64         // floats
#define PP_STRIDE 17         // u64 (16 keys + 1 pad -> ty groups 8 banks apart)
#define PCHUNK    16
#define SMEM_Q   (64 * QS_STRIDE * 4)   // 32768
#define SMEM_K   (64 * KS_STRIDE * 4)   // 16384
#define SMEM_V   (64 * KS_STRIDE * 4)   // 16384
#define SMEM_P   (64 * PP_STRIDE * 8)   // 8704
#define SMEM_ATTN (SMEM_Q + SMEM_K + SMEM_V + SMEM_P)   // 74240

__global__ __launch_bounds__(128, 3)
void attn_kernel()
{
    extern __shared__ char smraw[];
    float* Qs = (float*)smraw;                           // [64 dk][128]  Qs[dk][row]
    float* Ks = (float*)(smraw + SMEM_Q);                // [64 dk][64]   Ks[dk][key]
    float* Vs = (float*)(smraw + SMEM_Q + SMEM_K);       // [64 key][64]  Vs[key][dk]
    u64*   Pp = (u64*)(smraw + SMEM_Q + SMEM_K + SMEM_V);// [64 rowpair][17] chunk buf

    const int tid = threadIdx.x;
    const int tx  = tid & 7;          // 8 cols of 8
    const int ty  = tid >> 3;         // 16 rows of 8
    const int qt  = (SS / QT - 1) - blockIdx.x;   // heaviest first
    const int h   = blockIdx.y;
    const int b   = blockIdx.z;

    const size_t ho_t = (size_t)(b * HH + h) * DK * SS;   // Qt/Kt base
    const size_t ho_v = (size_t)(b * HH + h) * SS * DK;   // V base

    // ---- stage Q tile: 64 dk x 128 rows = 2048 float4 over 128 thr ----
    #pragma unroll
    for (int u = 0; u < 16; u++) {
        const int idx = u * 128 + tid;
        const int dk  = idx >> 5;       // 0..63
        const int rg  = idx & 31;       // float4 group 0..31
        float4 v = *(const float4*)(g_Qt + ho_t + (size_t)dk * SS + qt * QT + rg * 4);
        *(float4*)&Qs[dk * QS_STRIDE + rg * 4] = v;
    }

    u64 acc2[4][8];
    #pragma unroll
    for (int i = 0; i < 4; i++)
        #pragma unroll
        for (int j = 0; j < 8; j++) acc2[i][j] = 0ull;

    float m[8], l[8];
    #pragma unroll
    for (int r = 0; r < 8; r++) { m[r] = -1e30f; l[r] = 0.f; }

    const float scale = 0.125f;   // 1/sqrt(64)
    const int ntiles = 2 * qt + 2;

    for (int kt = 0; kt < ntiles; kt++) {
        __syncthreads();
        // ---- stage K (dk-major) and V (key-major) tiles ----
        #pragma unroll
        for (int u = 0; u < 8; u++) {
            const int idx = u * 128 + tid;
            const int row = idx >> 4;       // 0..63
            const int g4  = idx & 15;       // float4 group 0..15
            float4 kv = *(const float4*)(g_Kt + ho_t + (size_t)row * SS + kt * KT + g4 * 4);
            *(float4*)&Ks[row * KS_STRIDE + g4 * 4] = kv;
            float4 vv = *(const float4*)(g_V + ho_v + (size_t)(kt * KT + row) * DK + g4 * 4);
            *(float4*)&Vs[row * KS_STRIDE + g4 * 4] = vv;
        }
        __syncthreads();

        // ---- QK^T: 8x8 score micro-tile ----
        u64 s2[4][8];
        #pragma unroll
        for (int i = 0; i < 4; i++)
            #pragma unroll
            for (int j = 0; j < 8; j++) s2[i][j] = 0ull;

        const float* QsT = Qs + ty * 8;
        const float* KsT = Ks + tx * 8;
        #pragma unroll 4
        for (int dk = 0; dk < 64; dk++) {
            ulonglong2 qlo = *(const ulonglong2*)(QsT + dk * QS_STRIDE);
            ulonglong2 qhi = *(const ulonglong2*)(QsT + dk * QS_STRIDE + 4);
            float4 ka = *(const float4*)(KsT + dk * KS_STRIDE);
            float4 kb = *(const float4*)(KsT + dk * KS_STRIDE + 4);
            const u64 k0 = pack2(ka.x), k1 = pack2(ka.y), k2 = pack2(ka.z), k3 = pack2(ka.w);
            const u64 k4 = pack2(kb.x), k5 = pack2(kb.y), k6 = pack2(kb.z), k7 = pack2(kb.w);
            s2[0][0] = ffma2(qlo.x, k0, s2[0][0]);  s2[0][1] = ffma2(qlo.x, k1, s2[0][1]);
            s2[0][2] = ffma2(qlo.x, k2, s2[0][2]);  s2[0][3] = ffma2(qlo.x, k3, s2[0][3]);
            s2[0][4] = ffma2(qlo.x, k4, s2[0][4]);  s2[0][5] = ffma2(qlo.x, k5, s2[0][5]);
            s2[0][6] = ffma2(qlo.x, k6, s2[0][6]);  s2[0][7] = ffma2(qlo.x, k7, s2[0][7]);
            s2[1][0] = ffma2(qlo.y, k0, s2[1][0]);  s2[1][1] = ffma2(qlo.y, k1, s2[1][1]);
            s2[1][2] = ffma2(qlo.y, k2, s2[1][2]);  s2[1][3] = ffma2(qlo.y, k3, s2[1][3]);
            s2[1][4] = ffma2(qlo.y, k4, s2[1][4]);  s2[1][5] = ffma2(qlo.y, k5, s2[1][5]);
            s2[1][6] = ffma2(qlo.y, k6, s2[1][6]);  s2[1][7] = ffma2(qlo.y, k7, s2[1][7]);
            s2[2][0] = ffma2(qhi.x, k0, s2[2][0]);  s2[2][1] = ffma2(qhi.x, k1, s2[2][1]);
            s2[2][2] = ffma2(qhi.x, k2, s2[2][2]);  s2[2][3] = ffma2(qhi.x, k3, s2[2][3]);
            s2[2][4] = ffma2(qhi.x, k4, s2[2][4]);  s2[2][5] = ffma2(qhi.x, k5, s2[2][5]);
            s2[2][6] = ffma2(qhi.x, k6, s2[2][6]);  s2[2][7] = ffma2(qhi.x, k7, s2[2][7]);
            s2[3][0] = ffma2(qhi.y, k0, s2[3][0]);  s2[3][1] = ffma2(qhi.y, k1, s2[3][1]);
            s2[3][2] = ffma2(qhi.y, k2, s2[3][2]);  s2[3][3] = ffma2(qhi.y, k3, s2[3][3]);
            s2[3][4] = ffma2(qhi.y, k4, s2[3][4]);  s2[3][5] = ffma2(qhi.y, k5, s2[3][5]);
            s2[3][6] = ffma2(qhi.y, k6, s2[3][6]);  s2[3][7] = ffma2(qhi.y, k7, s2[3][7]);
        }

        // ---- unpack scores, scale, causal mask ----
        float p[8][8];
        #pragma unroll
        for (int rp = 0; rp < 4; rp++)
            #pragma unroll
            for (int c = 0; c < 8; c++) {
                float2 v = unpack2(s2[rp][c]);
                p[2 * rp][c]     = v.x * scale;
                p[2 * rp + 1][c] = v.y * scale;
            }

        if (kt >= 2 * qt) {   // diagonal tiles only
            const int rbase = qt * QT + ty * 8 - kt * KT;
            #pragma unroll
            for (int r = 0; r < 8; r++) {
                const int lim = rbase + r;
                #pragma unroll
                for (int c = 0; c < 8; c++)
                    if (tx * 8 + c > lim) p[r][c] = -1e30f;
            }
        }

        // ---- online softmax (row reductions over 8 tx lanes) ----
        float cc[8];
        #pragma unroll
        for (int r = 0; r < 8; r++) {
            float mx = fmaxf(fmaxf(fmaxf(p[r][0], p[r][1]), fmaxf(p[r][2], p[r][3])),
                             fmaxf(fmaxf(p[r][4], p[r][5]), fmaxf(p[r][6], p[r][7])));
            mx = fmaxf(mx, __shfl_xor_sync(0xffffffffu, mx, 1, 8));
            mx = fmaxf(mx, __shfl_xor_sync(0xffffffffu, mx, 2, 8));
            mx = fmaxf(mx, __shfl_xor_sync(0xffffffffu, mx, 4, 8));
            const float mn = fmaxf(m[r], mx);
            cc[r] = __expf(m[r] - mn);
            l[r] *= cc[r];
            m[r] = mn;
        }
        #pragma unroll
        for (int rp = 0; rp < 4; rp++) {
            const u64 ccp = packpair(cc[2 * rp], cc[2 * rp + 1]);
            #pragma unroll
            for (int c = 0; c < 8; c++) acc2[rp][c] = fmul2(acc2[rp][c], ccp);
        }
        #pragma unroll
        for (int r = 0; r < 8; r++) {
            #pragma unroll
            for (int c = 0; c < 8; c++) p[r][c] = __expf(p[r][c] - m[r]);
            float rs = ((p[r][0] + p[r][1]) + (p[r][2] + p[r][3]))
                     + ((p[r][4] + p[r][5]) + (p[r][6] + p[r][7]));
            rs += __shfl_xor_sync(0xffffffffu, rs, 1, 8);
            rs += __shfl_xor_sync(0xffffffffu, rs, 2, 8);
            rs += __shfl_xor_sync(0xffffffffu, rs, 4, 8);
            l[r] += rs;
        }

        // ---- PV in 4 chunks of 16 keys through the small P buffer ----
        // Pp rows are warp-private (ty*4+rp spans disjoint sets per warp),
        // so only __syncwarp() is needed around each chunk.
        const float* VsT = Vs + tx * 8;
        const u64*   PpT = Pp + (ty * 4) * PP_STRIDE;
        const int    mych = tx >> 1;            // chunk this thread's keys belong to
        const int    col0 = (tx & 1) * 8;       // chunk-local column base

        #pragma unroll
        for (int ch = 0; ch < 4; ch++) {
            if (mych == ch) {
                #pragma unroll
                for (int rp = 0; rp < 4; rp++) {
                    u64* dst = Pp + (ty * 4 + rp) * PP_STRIDE + col0;
                    #pragma unroll
                    for (int c = 0; c < 8; c++)
                        dst[c] = packpair(p[2 * rp][c], p[2 * rp + 1][c]);
                }
            }
            __syncwarp();

            #pragma unroll 2
            for (int j = 0; j < PCHUNK; j++) {
                const int jj = ch * PCHUNK + j;
                const u64 pA = PpT[j];
                const u64 pB = PpT[PP_STRIDE + j];
                const u64 pC = PpT[2 * PP_STRIDE + j];
                const u64 pD = PpT[3 * PP_STRIDE + j];
                float4 va = *(const float4*)(VsT + jj * KS_STRIDE);
                float4 vb = *(const float4*)(VsT + jj * KS_STRIDE + 4);
                const u64 v0 = pack2(va.x), v1 = pack2(va.y), v2 = pack2(va.z), v3 = pack2(va.w);
                const u64 v4 = pack2(vb.x), v5 = pack2(vb.y), v6 = pack2(vb.z), v7 = pack2(vb.w);
                acc2[0][0] = ffma2(pA, v0, acc2[0][0]);  acc2[0][1] = ffma2(pA, v1, acc2[0][1]);
                acc2[0][2] = ffma2(pA, v2, acc2[0][2]);  acc2[0][3] = ffma2(pA, v3, acc2[0][3]);
                acc2[0][4] = ffma2(pA, v4, acc2[0][4]);  acc2[0][5] = ffma2(pA, v5, acc2[0][5]);
                acc2[0][6] = ffma2(pA, v6, acc2[0][6]);  acc2[0][7] = ffma2(pA, v7, acc2[0][7]);
                acc2[1][0] = ffma2(pB, v0, acc2[1][0]);  acc2[1][1] = ffma2(pB, v1, acc2[1][1]);
                acc2[1][2] = ffma2(pB, v2, acc2[1][2]);  acc2[1][3] = ffma2(pB, v3, acc2[1][3]);
                acc2[1][4] = ffma2(pB, v4, acc2[1][4]);  acc2[1][5] = ffma2(pB, v5, acc2[1][5]);
                acc2[1][6] = ffma2(pB, v6, acc2[1][6]);  acc2[1][7] = ffma2(pB, v7, acc2[1][7]);
                acc2[2][0] = ffma2(pC, v0, acc2[2][0]);  acc2[2][1] = ffma2(pC, v1, acc2[2][1]);
                acc2[2][2] = ffma2(pC, v2, acc2[2][2]);  acc2[2][3] = ffma2(pC, v3, acc2[2][3]);
                acc2[2][4] = ffma2(pC, v4, acc2[2][4]);  acc2[2][5] = ffma2(pC, v5, acc2[2][5]);
                acc2[2][6] = ffma2(pC, v6, acc2[2][6]);  acc2[2][7] = ffma2(pC, v7, acc2[2][7]);
                acc2[3][0] = ffma2(pD, v0, acc2[3][0]);  acc2[3][1] = ffma2(pD, v1, acc2[3][1]);
                acc2[3][2] = ffma2(pD, v2, acc2[3][2]);  acc2[3][3] = ffma2(pD, v3, acc2[3][3]);
                acc2[3][4] = ffma2(pD, v4, acc2[3][4]);  acc2[3][5] = ffma2(pD, v5, acc2[3][5]);
                acc2[3][6] = ffma2(pD, v6, acc2[3][6]);  acc2[3][7] = ffma2(pD, v7, acc2[3][7]);
            }
            __syncwarp();
        }
    }

    // ---- epilogue: normalize and write ----
    #pragma unroll
    for (int rp = 0; rp < 4; rp++) {
        const float inv0 = 1.f / l[2 * rp];
        const float inv1 = 1.f / l[2 * rp + 1];
        float o0[8], o1[8];
        #pragma unroll
        for (int c = 0; c < 8; c++) {
            float2 v = unpack2(acc2[rp][c]);
            o0[c] = v.x * inv0;
            o1[c] = v.y * inv1;
        }
        const size_t row0 = (size_t)(b * SS + qt * QT + ty * 8 + 2 * rp);
        float* dst0 = g_att + row0 * DD + h * DK + tx * 8;
        *(float4*)dst0            = make_float4(o0[0], o0[1], o0[2], o0[3]);
        *(float4*)(dst0 + 4)      = make_float4(o0[4], o0[5], o0[6], o0[7]);
        *(float4*)(dst0 + DD)     = make_float4(o1[0], o1[1], o1[2], o1[3]);
        *(float4*)(dst0 + DD + 4) = make_float4(o1[4], o1[5], o1[6], o1[7]);
    }
}

// ---------------------------------------------------------------------------
// Launch
// ---------------------------------------------------------------------------
extern "C" void kernel_launch(void* const* d_in, const int* in_sizes, int n_in,
                              void* d_out, int out_size)
{
    const float* x  = (const float*)d_in[0];
    const float* Wq = (const float*)d_in[1];
    const float* bq = (const float*)d_in[2];
    const float* Wk = (const float*)d_in[3];
    const float* bk = (const float*)d_in[4];
    const float* Wv = (const float*)d_in[5];
    const float* bv = (const float*)d_in[6];
    const float* Wo = (const float*)d_in[7];
    const float* bo = (const float*)d_in[8];
    float* out = (float*)d_out;

    dim3 ggrid(DD / 128, MM / 64);   // (4, 128)

    gemm_bias_kernel<<<ggrid, 256>>>(x, Wq, bq, nullptr, 0);
    gemm_bias_kernel<<<ggrid, 256>>>(x, Wk, bk, nullptr, 1);
    gemm_bias_kernel<<<ggrid, 256>>>(x, Wv, bv, nullptr, 2);

    cudaFuncSetAttribute(attn_kernel,
                         cudaFuncAttributeMaxDynamicSharedMemorySize,
                         SMEM_ATTN);
    attn_kernel<<<dim3(SS / QT, HH, BB), 128, SMEM_ATTN>>>();

    gemm_bias_kernel<<<ggrid, 256>>>(nullptr, Wo, bo, out, 3);
}

// round 15
// speedup vs baseline: 1.0986x; 1.0986x over previous
#include <cuda_runtime.h>

// Problem constants
#define BB 2
#define SS 4096
#define DD 512
#define HH 8
#define DK 64
#define MM (BB * SS)   // 8192 rows
#define QT 128         // q rows per attention block
#define KT 64          // k cols per attention tile

// ---------------------------------------------------------------------------
// Scratch (device globals — no runtime allocation)
// g_Qt / g_Kt are TRANSPOSED per head: [b][h][dk][s]  (dk-major)
// g_V natural: [b][h][s][dk]
// ---------------------------------------------------------------------------
__device__ __align__(16) float g_Qt[BB * HH * DK * SS];
__device__ __align__(16) float g_Kt[BB * HH * DK * SS];
__device__ __align__(16) float g_V [BB * HH * SS * DK];
__device__ __align__(16) float g_att[BB * SS * DD];       // [B,S,D]

// ---------------------------------------------------------------------------
// Packed fp32x2 + cp.async helpers
// ---------------------------------------------------------------------------
typedef unsigned long long u64;
typedef unsigned int u32;

__device__ __forceinline__ u64 ffma2(u64 a, u64 b, u64 c) {
    u64 d;
    asm("fma.rn.f32x2 %0, %1, %2, %3;" : "=l"(d) : "l"(a), "l"(b), "l"(c));
    return d;
}
__device__ __forceinline__ u64 fmul2(u64 a, u64 b) {
    u64 d;
    asm("mul.rn.f32x2 %0, %1, %2;" : "=l"(d) : "l"(a), "l"(b));
    return d;
}
__device__ __forceinline__ u64 pack2(float x) {
    u64 d;
    asm("mov.b64 %0, {%1, %1};" : "=l"(d) : "f"(x));
    return d;
}
__device__ __forceinline__ u64 packpair(float a, float b) {
    u64 d;
    asm("mov.b64 %0, {%1, %2};" : "=l"(d) : "f"(a), "f"(b));
    return d;
}
__device__ __forceinline__ float2 unpack2(u64 v) {
    float2 r;
    asm("mov.b64 {%0, %1}, %2;" : "=f"(r.x), "=f"(r.y) : "l"(v));
    return r;
}
__device__ __forceinline__ void cp16(void* smem_dst, const void* gmem_src) {
    u32 s = (u32)__cvta_generic_to_shared(smem_dst);
    asm volatile("cp.async.cg.shared.global [%0], [%1], 16;" :: "r"(s), "l"(gmem_src));
}
#define CP_COMMIT() asm volatile("cp.async.commit_group;")
#define CP_WAIT0()  asm volatile("cp.async.wait_group 0;")

// ---------------------------------------------------------------------------
// GEMM body (shared by QKV-fused and O kernels).
//   C[i,j] = sum_k A[i,k] * W[j,k] + bias[j]
//   Next k-tile is LDG-prefetched right after the STS of the current tile,
//   so the L2 latency hides under the 16-step FFMA2 compute.
//   mode 0/1: write TRANSPOSED into g_Qt/g_Kt  ([b][h][dk][s])
//   mode 2  : write natural into g_V           ([b][h][s][dk])
//   mode 3  : plain row-major into Cout
// ---------------------------------------------------------------------------
__device__ __forceinline__
void gemm_body(const float* __restrict__ Ap,
               const float* __restrict__ W,
               const float* __restrict__ bias,
               float* __restrict__ Cout,
               int mode, int bm, int bn)
{
    __shared__ __align__(16) float As[16][64];
    __shared__ __align__(16) float Bs[16][128];

    const int tid = threadIdx.x;
    const int tx  = tid & 15;
    const int ty  = tid >> 4;

    const int lrow = tid >> 2;
    const int lk4  = (tid & 3) << 2;

    const float* Aptr  = Ap + (size_t)(bm * 64 + lrow) * DD + lk4;
    const float* Wptr0 = W  + (size_t)(bn * 128 + lrow) * DD + lk4;
    const float* Wptr1 = Wptr0 + (size_t)64 * DD;

    u64 c[16];
    #pragma unroll
    for (int i = 0; i < 16; i++) c[i] = 0ull;

    // prefetch tile 0
    float4 a4 = *(const float4*)(Aptr);
    float4 w0 = *(const float4*)(Wptr0);
    float4 w1 = *(const float4*)(Wptr1);

    for (int kk = 0; kk < DD; kk += 16) {
        __syncthreads();   // previous iter's reads done
        As[lk4 + 0][lrow] = a4.x;  As[lk4 + 1][lrow] = a4.y;
        As[lk4 + 2][lrow] = a4.z;  As[lk4 + 3][lrow] = a4.w;
        Bs[lk4 + 0][lrow] = w0.x;  Bs[lk4 + 1][lrow] = w0.y;
        Bs[lk4 + 2][lrow] = w0.z;  Bs[lk4 + 3][lrow] = w0.w;
        Bs[lk4 + 0][lrow + 64] = w1.x;  Bs[lk4 + 1][lrow + 64] = w1.y;
        Bs[lk4 + 2][lrow + 64] = w1.z;  Bs[lk4 + 3][lrow + 64] = w1.w;

        // issue next tile's loads NOW — consumed only after full compute
        if (kk + 16 < DD) {
            a4 = *(const float4*)(Aptr  + kk + 16);
            w0 = *(const float4*)(Wptr0 + kk + 16);
            w1 = *(const float4*)(Wptr1 + kk + 16);
        }
        __syncthreads();

        #pragma unroll
        for (int k = 0; k < 16; k++) {
            float4 av = *(const float4*)&As[k][ty << 2];
            const u64* bp = (const u64*)&Bs[k][tx << 3];
            u64 b0 = bp[0], b1 = bp[1], b2 = bp[2], b3 = bp[3];
            u64 ax = pack2(av.x), ay = pack2(av.y);
            u64 az = pack2(av.z), aw = pack2(av.w);
            c[0]  = ffma2(ax, b0, c[0]);  c[1]  = ffma2(ax, b1, c[1]);
            c[2]  = ffma2(ax, b2, c[2]);  c[3]  = ffma2(ax, b3, c[3]);
            c[4]  = ffma2(ay, b0, c[4]);  c[5]  = ffma2(ay, b1, c[5]);
            c[6]  = ffma2(ay, b2, c[6]);  c[7]  = ffma2(ay, b3, c[7]);
            c[8]  = ffma2(az, b0, c[8]);  c[9]  = ffma2(az, b1, c[9]);
            c[10] = ffma2(az, b2, c[10]); c[11] = ffma2(az, b3, c[11]);
            c[12] = ffma2(aw, b0, c[12]); c[13] = ffma2(aw, b1, c[13]);
            c[14] = ffma2(aw, b2, c[14]); c[15] = ffma2(aw, b3, c[15]);
        }
    }

    const int r0 = bm * 64 + (ty << 2);
    const int c0 = bn * 128 + (tx << 3);
    float* qkv = (mode == 0) ? g_Qt : (mode == 1) ? g_Kt : g_V;

    #pragma unroll
    for (int i = 0; i < 4; i++) {
        const int row = r0 + i;
        #pragma unroll
        for (int jp = 0; jp < 4; jp++) {
            float2 cv = unpack2(c[i * 4 + jp]);
            const int col0 = c0 + jp * 2;
            float v0 = cv.x + bias[col0];
            float v1 = cv.y + bias[col0 + 1];
            if (mode < 2) {
                const int b  = row >> 12;
                const int s  = row & 4095;
                const int h  = col0 >> 6;
                const int dk = col0 & 63;
                float* base = &qkv[((size_t)(b * HH + h) * DK + dk) * SS + s];
                base[0]  = v0;
                base[SS] = v1;
            } else if (mode == 2) {
                const int b  = row >> 12;
                const int s  = row & 4095;
                const int h  = col0 >> 6;
                const int dk = col0 & 63;
                float* dst = &qkv[(((size_t)(b * HH + h) << 12) + s) * DK + dk];
                dst[0] = v0;  dst[1] = v1;
            } else {
                float* dst = &Cout[(size_t)row * DD + col0];
                dst[0] = v0;  dst[1] = v1;
            }
        }
    }
}

// Fused Q/K/V projections: blockIdx.z selects the projection. Shared A -> L2 reuse.
__global__ __launch_bounds__(256)
void gemm_qkv_kernel(const float* __restrict__ x,
                     const float* __restrict__ Wq, const float* __restrict__ bq,
                     const float* __restrict__ Wk, const float* __restrict__ bk,
                     const float* __restrict__ Wv, const float* __restrict__ bv)
{
    const int mode = blockIdx.z;
    const float* W    = (mode == 0) ? Wq : (mode == 1) ? Wk : Wv;
    const float* bias = (mode == 0) ? bq : (mode == 1) ? bk : bv;
    gemm_body(x, W, bias, nullptr, mode, blockIdx.y, blockIdx.x);
}

// Output projection.
__global__ __launch_bounds__(256)
void gemm_o_kernel(const float* __restrict__ Wo, const float* __restrict__ bo,
                   float* __restrict__ out)
{
    gemm_body(g_att, Wo, bo, out, 3, blockIdx.y, blockIdx.x);
}

// ---------------------------------------------------------------------------
// Register-tiled causal flash attention, 8x8 micro-tile,
// cp.async double-buffered K/V staging (one barrier per tile).
// Block 128 thr: tx 0..7 (8 keys / 8 dk-cols each), ty 0..15 (8 q rows each).
// ---------------------------------------------------------------------------
#define QS_STRIDE 128        // floats
#define KS_STRIDE 64         // floats
#define KS_SZ     (64 * KS_STRIDE)   // floats per K/V stage
#define PP_STRIDE 17         // u64
#define PCHUNK    16
#define SMEM_Q   (64 * QS_STRIDE * 4)   // 32768
#define SMEM_K   (2 * KS_SZ * 4)        // 32768
#define SMEM_V   (2 * KS_SZ * 4)        // 32768
#define SMEM_P   (64 * PP_STRIDE * 8)   // 8704
#define SMEM_ATTN (SMEM_Q + SMEM_K + SMEM_V + SMEM_P)   // 107008

__global__ __launch_bounds__(128)
void attn_kernel()
{
    extern __shared__ char smraw[];
    float* Qs = (float*)smraw;                           // [64 dk][128]
    float* Ks = (float*)(smraw + SMEM_Q);                // [2][64 dk][64 key]
    float* Vs = (float*)(smraw + SMEM_Q + SMEM_K);       // [2][64 key][64 dk]
    u64*   Pp = (u64*)(smraw + SMEM_Q + SMEM_K + SMEM_V);// [64 rowpair][17]

    const int tid = threadIdx.x;
    const int tx  = tid & 7;
    const int ty  = tid >> 3;
    const int qt  = (SS / QT - 1) - blockIdx.x;   // heaviest first
    const int h   = blockIdx.y;
    const int b   = blockIdx.z;

    const size_t ho_t = (size_t)(b * HH + h) * DK * SS;   // Qt/Kt base
    const size_t ho_v = (size_t)(b * HH + h) * SS * DK;   // V base

    const int srow = tid >> 4;       // staging row 0..7 base
    const int sg4  = tid & 15;       // staging float4 group

    // ---- prefetch K/V tile 0 via cp.async ----
    #pragma unroll
    for (int u = 0; u < 8; u++) {
        const int row = u * 8 + srow;
        cp16(&Ks[row * KS_STRIDE + sg4 * 4],
             g_Kt + ho_t + (size_t)row * SS + sg4 * 4);
        cp16(&Vs[row * KS_STRIDE + sg4 * 4],
             g_V + ho_v + (size_t)row * DK + sg4 * 4);
    }
    CP_COMMIT();

    // ---- stage Q tile (overlaps with the in-flight cp.async group) ----
    #pragma unroll
    for (int u = 0; u < 16; u++) {
        const int idx = u * 128 + tid;
        const int dk  = idx >> 5;
        const int rg  = idx & 31;
        float4 v = *(const float4*)(g_Qt + ho_t + (size_t)dk * SS + qt * QT + rg * 4);
        *(float4*)&Qs[dk * QS_STRIDE + rg * 4] = v;
    }

    u64 acc2[4][8];
    #pragma unroll
    for (int i = 0; i < 4; i++)
        #pragma unroll
        for (int j = 0; j < 8; j++) acc2[i][j] = 0ull;

    float m[8], l[8];
    #pragma unroll
    for (int r = 0; r < 8; r++) { m[r] = -1e30f; l[r] = 0.f; }

    const float scale = 0.125f;   // 1/sqrt(64)
    const int ntiles = 2 * qt + 2;

    CP_WAIT0();
    __syncthreads();

    for (int kt = 0; kt < ntiles; kt++) {
        // ---- prefetch next K/V tile into the other buffer ----
        if (kt + 1 < ntiles) {
            const int nb = (kt + 1) & 1;
            const size_t kcol = (size_t)(kt + 1) * KT;
            #pragma unroll
            for (int u = 0; u < 8; u++) {
                const int row = u * 8 + srow;
                cp16(&Ks[nb * KS_SZ + row * KS_STRIDE + sg4 * 4],
                     g_Kt + ho_t + (size_t)row * SS + kcol + sg4 * 4);
                cp16(&Vs[nb * KS_SZ + row * KS_STRIDE + sg4 * 4],
                     g_V + ho_v + (kcol + row) * DK + sg4 * 4);
            }
            CP_COMMIT();
        }

        const float* Kbuf = Ks + (kt & 1) * KS_SZ;
        const float* Vbuf = Vs + (kt & 1) * KS_SZ;

        // ---- QK^T: 8x8 score micro-tile ----
        u64 s2[4][8];
        #pragma unroll
        for (int i = 0; i < 4; i++)
            #pragma unroll
            for (int j = 0; j < 8; j++) s2[i][j] = 0ull;

        const float* QsT = Qs + ty * 8;
        const float* KsT = Kbuf + tx * 8;
        #pragma unroll 4
        for (int dk = 0; dk < 64; dk++) {
            ulonglong2 qlo = *(const ulonglong2*)(QsT + dk * QS_STRIDE);
            ulonglong2 qhi = *(const ulonglong2*)(QsT + dk * QS_STRIDE + 4);
            float4 ka = *(const float4*)(KsT + dk * KS_STRIDE);
            float4 kb = *(const float4*)(KsT + dk * KS_STRIDE + 4);
            const u64 k0 = pack2(ka.x), k1 = pack2(ka.y), k2 = pack2(ka.z), k3 = pack2(ka.w);
            const u64 k4 = pack2(kb.x), k5 = pack2(kb.y), k6 = pack2(kb.z), k7 = pack2(kb.w);
            s2[0][0] = ffma2(qlo.x, k0, s2[0][0]);  s2[0][1] = ffma2(qlo.x, k1, s2[0][1]);
            s2[0][2] = ffma2(qlo.x, k2, s2[0][2]);  s2[0][3] = ffma2(qlo.x, k3, s2[0][3]);
            s2[0][4] = ffma2(qlo.x, k4, s2[0][4]);  s2[0][5] = ffma2(qlo.x, k5, s2[0][5]);
            s2[0][6] = ffma2(qlo.x, k6, s2[0][6]);  s2[0][7] = ffma2(qlo.x, k7, s2[0][7]);
            s2[1][0] = ffma2(qlo.y, k0, s2[1][0]);  s2[1][1] = ffma2(qlo.y, k1, s2[1][1]);
            s2[1][2] = ffma2(qlo.y, k2, s2[1][2]);  s2[1][3] = ffma2(qlo.y, k3, s2[1][3]);
            s2[1][4] = ffma2(qlo.y, k4, s2[1][4]);  s2[1][5] = ffma2(qlo.y, k5, s2[1][5]);
            s2[1][6] = ffma2(qlo.y, k6, s2[1][6]);  s2[1][7] = ffma2(qlo.y, k7, s2[1][7]);
            s2[2][0] = ffma2(qhi.x, k0, s2[2][0]);  s2[2][1] = ffma2(qhi.x, k1, s2[2][1]);
            s2[2][2] = ffma2(qhi.x, k2, s2[2][2]);  s2[2][3] = ffma2(qhi.x, k3, s2[2][3]);
            s2[2][4] = ffma2(qhi.x, k4, s2[2][4]);  s2[2][5] = ffma2(qhi.x, k5, s2[2][5]);
            s2[2][6] = ffma2(qhi.x, k6, s2[2][6]);  s2[2][7] = ffma2(qhi.x, k7, s2[2][7]);
            s2[3][0] = ffma2(qhi.y, k0, s2[3][0]);  s2[3][1] = ffma2(qhi.y, k1, s2[3][1]);
            s2[3][2] = ffma2(qhi.y, k2, s2[3][2]);  s2[3][3] = ffma2(qhi.y, k3, s2[3][3]);
            s2[3][4] = ffma2(qhi.y, k4, s2[3][4]);  s2[3][5] = ffma2(qhi.y, k5, s2[3][5]);
            s2[3][6] = ffma2(qhi.y, k6, s2[3][6]);  s2[3][7] = ffma2(qhi.y, k7, s2[3][7]);
        }

        // ---- unpack scores, scale, causal mask ----
        float p[8][8];
        #pragma unroll
        for (int rp = 0; rp < 4; rp++)
            #pragma unroll
            for (int c = 0; c < 8; c++) {
                float2 v = unpack2(s2[rp][c]);
                p[2 * rp][c]     = v.x * scale;
                p[2 * rp + 1][c] = v.y * scale;
            }

        if (kt >= 2 * qt) {   // diagonal tiles only
            const int rbase = qt * QT + ty * 8 - kt * KT;
            #pragma unroll
            for (int r = 0; r < 8; r++) {
                const int lim = rbase + r;
                #pragma unroll
                for (int c = 0; c < 8; c++)
                    if (tx * 8 + c > lim) p[r][c] = -1e30f;
            }
        }

        // ---- online softmax (row reductions over 8 tx lanes) ----
        float cc[8];
        #pragma unroll
        for (int r = 0; r < 8; r++) {
            float mx = fmaxf(fmaxf(fmaxf(p[r][0], p[r][1]), fmaxf(p[r][2], p[r][3])),
                             fmaxf(fmaxf(p[r][4], p[r][5]), fmaxf(p[r][6], p[r][7])));
            mx = fmaxf(mx, __shfl_xor_sync(0xffffffffu, mx, 1, 8));
            mx = fmaxf(mx, __shfl_xor_sync(0xffffffffu, mx, 2, 8));
            mx = fmaxf(mx, __shfl_xor_sync(0xffffffffu, mx, 4, 8));
            const float mn = fmaxf(m[r], mx);
            cc[r] = __expf(m[r] - mn);
            l[r] *= cc[r];
            m[r] = mn;
        }
        #pragma unroll
        for (int rp = 0; rp < 4; rp++) {
            const u64 ccp = packpair(cc[2 * rp], cc[2 * rp + 1]);
            #pragma unroll
            for (int c = 0; c < 8; c++) acc2[rp][c] = fmul2(acc2[rp][c], ccp);
        }
        #pragma unroll
        for (int r = 0; r < 8; r++) {
            #pragma unroll
            for (int c = 0; c < 8; c++) p[r][c] = __expf(p[r][c] - m[r]);
            float rs = ((p[r][0] + p[r][1]) + (p[r][2] + p[r][3]))
                     + ((p[r][4] + p[r][5]) + (p[r][6] + p[r][7]));
            rs += __shfl_xor_sync(0xffffffffu, rs, 1, 8);
            rs += __shfl_xor_sync(0xffffffffu, rs, 2, 8);
            rs += __shfl_xor_sync(0xffffffffu, rs, 4, 8);
            l[r] += rs;
        }

        // ---- PV in 4 chunks of 16 keys through the small P buffer ----
        const float* VsT = Vbuf + tx * 8;
        const u64*   PpT = Pp + (ty * 4) * PP_STRIDE;
        const int    mych = tx >> 1;
        const int    col0 = (tx & 1) * 8;

        #pragma unroll
        for (int ch = 0; ch < 4; ch++) {
            if (mych == ch) {
                #pragma unroll
                for (int rp = 0; rp < 4; rp++) {
                    u64* dst = Pp + (ty * 4 + rp) * PP_STRIDE + col0;
                    #pragma unroll
                    for (int c = 0; c < 8; c++)
                        dst[c] = packpair(p[2 * rp][c], p[2 * rp + 1][c]);
                }
            }
            __syncwarp();

            #pragma unroll 2
            for (int j = 0; j < PCHUNK; j++) {
                const int jj = ch * PCHUNK + j;
                const u64 pA = PpT[j];
                const u64 pB = PpT[PP_STRIDE + j];
                const u64 pC = PpT[2 * PP_STRIDE + j];
                const u64 pD = PpT[3 * PP_STRIDE + j];
                float4 va = *(const float4*)(VsT + jj * KS_STRIDE);
                float4 vb = *(const float4*)(VsT + jj * KS_STRIDE + 4);
                const u64 v0 = pack2(va.x), v1 = pack2(va.y), v2 = pack2(va.z), v3 = pack2(va.w);
                const u64 v4 = pack2(vb.x), v5 = pack2(vb.y), v6 = pack2(vb.z), v7 = pack2(vb.w);
                acc2[0][0] = ffma2(pA, v0, acc2[0][0]);  acc2[0][1] = ffma2(pA, v1, acc2[0][1]);
                acc2[0][2] = ffma2(pA, v2, acc2[0][2]);  acc2[0][3] = ffma2(pA, v3, acc2[0][3]);
                acc2[0][4] = ffma2(pA, v4, acc2[0][4]);  acc2[0][5] = ffma2(pA, v5, acc2[0][5]);
                acc2[0][6] = ffma2(pA, v6, acc2[0][6]);  acc2[0][7] = ffma2(pA, v7, acc2[0][7]);
                acc2[1][0] = ffma2(pB, v0, acc2[1][0]);  acc2[1][1] = ffma2(pB, v1, acc2[1][1]);
                acc2[1][2] = ffma2(pB, v2, acc2[1][2]);  acc2[1][3] = ffma2(pB, v3, acc2[1][3]);
                acc2[1][4] = ffma2(pB, v4, acc2[1][4]);  acc2[1][5] = ffma2(pB, v5, acc2[1][5]);
                acc2[1][6] = ffma2(pB, v6, acc2[1][6]);  acc2[1][7] = ffma2(pB, v7, acc2[1][7]);
                acc2[2][0] = ffma2(pC, v0, acc2[2][0]);  acc2[2][1] = ffma2(pC, v1, acc2[2][1]);
                acc2[2][2] = ffma2(pC, v2, acc2[2][2]);  acc2[2][3] = ffma2(pC, v3, acc2[2][3]);
                acc2[2][4] = ffma2(pC, v4, acc2[2][4]);  acc2[2][5] = ffma2(pC, v5, acc2[2][5]);
                acc2[2][6] = ffma2(pC, v6, acc2[2][6]);  acc2[2][7] = ffma2(pC, v7, acc2[2][7]);
                acc2[3][0] = ffma2(pD, v0, acc2[3][0]);  acc2[3][1] = ffma2(pD, v1, acc2[3][1]);
                acc2[3][2] = ffma2(pD, v2, acc2[3][2]);  acc2[3][3] = ffma2(pD, v3, acc2[3][3]);
                acc2[3][4] = ffma2(pD, v4, acc2[3][4]);  acc2[3][5] = ffma2(pD, v5, acc2[3][5]);
                acc2[3][6] = ffma2(pD, v6, acc2[3][6]);  acc2[3][7] = ffma2(pD, v7, acc2[3][7]);
            }
            __syncwarp();
        }

        // ---- wait for next tile's fills; one barrier per tile ----
        CP_WAIT0();
        __syncthreads();
    }

    // ---- epilogue: normalize and write ----
    #pragma unroll
    for (int rp = 0; rp < 4; rp++) {
        const float inv0 = 1.f / l[2 * rp];
        const float inv1 = 1.f / l[2 * rp + 1];
        float o0[8], o1[8];
        #pragma unroll
        for (int c = 0; c < 8; c++) {
            float2 v = unpack2(acc2[rp][c]);
            o0[c] = v.x * inv0;
            o1[c] = v.y * inv1;
        }
        const size_t row0 = (size_t)(b * SS + qt * QT + ty * 8 + 2 * rp);
        float* dst0 = g_att + row0 * DD + h * DK + tx * 8;
        *(float4*)dst0            = make_float4(o0[0], o0[1], o0[2], o0[3]);
        *(float4*)(dst0 + 4)      = make_float4(o0[4], o0[5], o0[6], o0[7]);
        *(float4*)(dst0 + DD)     = make_float4(o1[0], o1[1], o1[2], o1[3]);
        *(float4*)(dst0 + DD + 4) = make_float4(o1[4], o1[5], o1[6], o1[7]);
    }
}

// ---------------------------------------------------------------------------
// Launch
// ---------------------------------------------------------------------------
extern "C" void kernel_launch(void* const* d_in, const int* in_sizes, int n_in,
                              void* d_out, int out_size)
{
    const float* x  = (const float*)d_in[0];
    const float* Wq = (const float*)d_in[1];
    const float* bq = (const float*)d_in[2];
    const float* Wk = (const float*)d_in[3];
    const float* bk = (const float*)d_in[4];
    const float* Wv = (const float*)d_in[5];
    const float* bv = (const float*)d_in[6];
    const float* Wo = (const float*)d_in[7];
    const float* bo = (const float*)d_in[8];
    float* out = (float*)d_out;

    dim3 qkv_grid(DD / 128, MM / 64, 3);   // (4, 128, 3)
    gemm_qkv_kernel<<<qkv_grid, 256>>>(x, Wq, bq, Wk, bk, Wv, bv);

    cudaFuncSetAttribute(attn_kernel,
                         cudaFuncAttributeMaxDynamicSharedMemorySize,
                         SMEM_ATTN);
    attn_kernel<<<dim3(SS / QT, HH, BB), 128, SMEM_ATTN>>>();

    dim3 o_grid(DD / 128, MM / 64);        // (4, 128)
    gemm_o_kernel<<<o_grid, 256>>>(Wo, bo, out);
}

// round 16
// speedup vs baseline: 1.2157x; 1.1066x over previous
#include <cuda_runtime.h>

// Problem constants
#define BB 2
#define SS 4096
#define DD 512
#define HH 8
#define DK 64
#define MM (BB * SS)   // 8192 rows
#define QT 128         // q rows per attention block
#define KT 64          // k cols per attention tile

// ---------------------------------------------------------------------------
// Scratch (device globals — no runtime allocation)
// g_Qt / g_Kt are TRANSPOSED per head: [b][h][dk][s]  (dk-major)
// g_V natural: [b][h][s][dk]
// ---------------------------------------------------------------------------
__device__ __align__(16) float g_Qt[BB * HH * DK * SS];
__device__ __align__(16) float g_Kt[BB * HH * DK * SS];
__device__ __align__(16) float g_V [BB * HH * SS * DK];
__device__ __align__(16) float g_att[BB * SS * DD];       // [B,S,D]

// ---------------------------------------------------------------------------
// Packed fp32x2 + cp.async helpers
// ---------------------------------------------------------------------------
typedef unsigned long long u64;
typedef unsigned int u32;

__device__ __forceinline__ u64 ffma2(u64 a, u64 b, u64 c) {
    u64 d;
    asm("fma.rn.f32x2 %0, %1, %2, %3;" : "=l"(d) : "l"(a), "l"(b), "l"(c));
    return d;
}
__device__ __forceinline__ u64 fmul2(u64 a, u64 b) {
    u64 d;
    asm("mul.rn.f32x2 %0, %1, %2;" : "=l"(d) : "l"(a), "l"(b));
    return d;
}
__device__ __forceinline__ u64 pack2(float x) {
    u64 d;
    asm("mov.b64 %0, {%1, %1};" : "=l"(d) : "f"(x));
    return d;
}
__device__ __forceinline__ u64 packpair(float a, float b) {
    u64 d;
    asm("mov.b64 %0, {%1, %2};" : "=l"(d) : "f"(a), "f"(b));
    return d;
}
__device__ __forceinline__ float2 unpack2(u64 v) {
    float2 r;
    asm("mov.b64 {%0, %1}, %2;" : "=f"(r.x), "=f"(r.y) : "l"(v));
    return r;
}
__device__ __forceinline__ void cp16(void* smem_dst, const void* gmem_src) {
    u32 s = (u32)__cvta_generic_to_shared(smem_dst);
    asm volatile("cp.async.cg.shared.global [%0], [%1], 16;" :: "r"(s), "l"(gmem_src));
}
#define CP_COMMIT() asm volatile("cp.async.commit_group;")
#define CP_WAIT0()  asm volatile("cp.async.wait_group 0;")

// ---------------------------------------------------------------------------
// GEMM body, 128x128 block tile, 8x8 micro-tile, row-pair packed accumulators.
//   C[i,j] = sum_k A[i,k] * W[j,k] + bias[j]
//   As[k][row]: A operand loads are u64 row-pairs, 16-lane BROADCAST (ty-indexed).
//   Bs[k][col]: 2 LDS.128 per k-step. 8 pack MOVs. 32 FFMA2 per k-step.
//   Next k-tile LDG-prefetched into registers during compute.
//   mode 0/1: write TRANSPOSED into g_Qt/g_Kt  ([b][h][dk][s])
//   mode 2  : write natural into g_V           ([b][h][s][dk])
//   mode 3  : plain row-major into Cout
// ---------------------------------------------------------------------------
__device__ __forceinline__
void gemm_body(const float* __restrict__ Ap,
               const float* __restrict__ W,
               const float* __restrict__ bias,
               float* __restrict__ Cout,
               int mode, int bm, int bn)
{
    __shared__ __align__(16) float As[16][128];
    __shared__ __align__(16) float Bs[16][128];

    const int tid = threadIdx.x;
    const int tx  = tid & 15;          // 0..15 -> cols tx*8..+7
    const int ty  = tid >> 4;          // 0..15 -> rows ty*8..+7

    // loaders: each thread owns one row and half its k-range (8 k's = 2 float4)
    const int lrow = tid >> 1;         // 0..127
    const int lk8  = (tid & 1) << 3;   // 0 or 8

    const float* Aptr = Ap + (size_t)(bm * 128 + lrow) * DD + lk8;
    const float* Wptr = W  + (size_t)(bn * 128 + lrow) * DD + lk8;

    u64 acc[4][8];                     // [row-pair][col]
    #pragma unroll
    for (int i = 0; i < 4; i++)
        #pragma unroll
        for (int j = 0; j < 8; j++) acc[i][j] = 0ull;

    // prefetch k-tile 0
    float4 a0 = *(const float4*)(Aptr);
    float4 a1 = *(const float4*)(Aptr + 4);
    float4 w0 = *(const float4*)(Wptr);
    float4 w1 = *(const float4*)(Wptr + 4);

    for (int kk = 0; kk < DD; kk += 16) {
        __syncthreads();   // previous iter's reads done
        As[lk8 + 0][lrow] = a0.x;  As[lk8 + 1][lrow] = a0.y;
        As[lk8 + 2][lrow] = a0.z;  As[lk8 + 3][lrow] = a0.w;
        As[lk8 + 4][lrow] = a1.x;  As[lk8 + 5][lrow] = a1.y;
        As[lk8 + 6][lrow] = a1.z;  As[lk8 + 7][lrow] = a1.w;
        Bs[lk8 + 0][lrow] = w0.x;  Bs[lk8 + 1][lrow] = w0.y;
        Bs[lk8 + 2][lrow] = w0.z;  Bs[lk8 + 3][lrow] = w0.w;
        Bs[lk8 + 4][lrow] = w1.x;  Bs[lk8 + 5][lrow] = w1.y;
        Bs[lk8 + 6][lrow] = w1.z;  Bs[lk8 + 7][lrow] = w1.w;

        // issue next tile's loads NOW — consumed after full compute
        if (kk + 16 < DD) {
            a0 = *(const float4*)(Aptr + kk + 16);
            a1 = *(const float4*)(Aptr + kk + 20);
            w0 = *(const float4*)(Wptr + kk + 16);
            w1 = *(const float4*)(Wptr + kk + 20);
        }
        __syncthreads();

        #pragma unroll
        for (int k = 0; k < 16; k++) {
            const u64* ap = (const u64*)&As[k][ty << 3];   // 4 row-pairs, broadcast
            const u64 ra = ap[0], rb = ap[1], rc = ap[2], rd = ap[3];
            float4 b03 = *(const float4*)&Bs[k][tx << 3];
            float4 b47 = *(const float4*)&Bs[k][(tx << 3) + 4];
            const u64 c0 = pack2(b03.x), c1 = pack2(b03.y);
            const u64 c2 = pack2(b03.z), c3 = pack2(b03.w);
            const u64 c4 = pack2(b47.x), c5 = pack2(b47.y);
            const u64 c6 = pack2(b47.z), c7 = pack2(b47.w);
            acc[0][0] = ffma2(ra, c0, acc[0][0]);  acc[0][1] = ffma2(ra, c1, acc[0][1]);
            acc[0][2] = ffma2(ra, c2, acc[0][2]);  acc[0][3] = ffma2(ra, c3, acc[0][3]);
            acc[0][4] = ffma2(ra, c4, acc[0][4]);  acc[0][5] = ffma2(ra, c5, acc[0][5]);
            acc[0][6] = ffma2(ra, c6, acc[0][6]);  acc[0][7] = ffma2(ra, c7, acc[0][7]);
            acc[1][0] = ffma2(rb, c0, acc[1][0]);  acc[1][1] = ffma2(rb, c1, acc[1][1]);
            acc[1][2] = ffma2(rb, c2, acc[1][2]);  acc[1][3] = ffma2(rb, c3, acc[1][3]);
            acc[1][4] = ffma2(rb, c4, acc[1][4]);  acc[1][5] = ffma2(rb, c5, acc[1][5]);
            acc[1][6] = ffma2(rb, c6, acc[1][6]);  acc[1][7] = ffma2(rb, c7, acc[1][7]);
            acc[2][0] = ffma2(rc, c0, acc[2][0]);  acc[2][1] = ffma2(rc, c1, acc[2][1]);
            acc[2][2] = ffma2(rc, c2, acc[2][2]);  acc[2][3] = ffma2(rc, c3, acc[2][3]);
            acc[2][4] = ffma2(rc, c4, acc[2][4]);  acc[2][5] = ffma2(rc, c5, acc[2][5]);
            acc[2][6] = ffma2(rc, c6, acc[2][6]);  acc[2][7] = ffma2(rc, c7, acc[2][7]);
            acc[3][0] = ffma2(rd, c0, acc[3][0]);  acc[3][1] = ffma2(rd, c1, acc[3][1]);
            acc[3][2] = ffma2(rd, c2, acc[3][2]);  acc[3][3] = ffma2(rd, c3, acc[3][3]);
            acc[3][4] = ffma2(rd, c4, acc[3][4]);  acc[3][5] = ffma2(rd, c5, acc[3][5]);
            acc[3][6] = ffma2(rd, c6, acc[3][6]);  acc[3][7] = ffma2(rd, c7, acc[3][7]);
        }
    }

    // ---- epilogue ----
    const int r00 = bm * 128 + (ty << 3);   // first of this thread's 8 rows
    const int c0  = bn * 128 + (tx << 3);   // first of this thread's 8 cols

    float bi[8];
    {
        float4 b03 = *(const float4*)&bias[c0];
        float4 b47 = *(const float4*)&bias[c0 + 4];
        bi[0] = b03.x; bi[1] = b03.y; bi[2] = b03.z; bi[3] = b03.w;
        bi[4] = b47.x; bi[5] = b47.y; bi[6] = b47.z; bi[7] = b47.w;
    }

    const int b_  = r00 >> 12;      // batch (block never spans batches)
    const int s00 = r00 & 4095;
    const int h   = c0 >> 6;        // head (8 cols never span heads)
    const int dk0 = c0 & 63;

    #pragma unroll
    for (int rp = 0; rp < 4; rp++) {
        float o0[8], o1[8];
        #pragma unroll
        for (int c = 0; c < 8; c++) {
            float2 v = unpack2(acc[rp][c]);
            o0[c] = v.x + bi[c];
            o1[c] = v.y + bi[c];
        }
        if (mode < 2) {
            // transposed: [b][h][dk][s]; row-pair -> s,s+1 contiguous
            float* qkv = (mode == 0) ? g_Qt : g_Kt;
            float* hb = &qkv[((size_t)(b_ * HH + h) * DK + dk0) * SS];
            const int s0 = s00 + 2 * rp;
            #pragma unroll
            for (int c = 0; c < 8; c++) {
                float* base = &hb[(size_t)c * SS + s0];
                base[0] = o0[c];
                base[1] = o1[c];
            }
        } else if (mode == 2) {
            // natural: [b][h][s][dk]; cols contiguous
            const int s0 = s00 + 2 * rp;
            float* dst0 = &g_V[(((size_t)(b_ * HH + h) << 12) + s0) * DK + dk0];
            *(float4*)dst0            = make_float4(o0[0], o0[1], o0[2], o0[3]);
            *(float4*)(dst0 + 4)      = make_float4(o0[4], o0[5], o0[6], o0[7]);
            *(float4*)(dst0 + DK)     = make_float4(o1[0], o1[1], o1[2], o1[3]);
            *(float4*)(dst0 + DK + 4) = make_float4(o1[4], o1[5], o1[6], o1[7]);
        } else {
            const int row0 = r00 + 2 * rp;
            float* dst0 = &Cout[(size_t)row0 * DD + c0];
            *(float4*)dst0            = make_float4(o0[0], o0[1], o0[2], o0[3]);
            *(float4*)(dst0 + 4)      = make_float4(o0[4], o0[5], o0[6], o0[7]);
            *(float4*)(dst0 + DD)     = make_float4(o1[0], o1[1], o1[2], o1[3]);
            *(float4*)(dst0 + DD + 4) = make_float4(o1[4], o1[5], o1[6], o1[7]);
        }
    }
}

// Fused Q/K/V projections: blockIdx.z selects the projection. Shared A -> L2 reuse.
__global__ __launch_bounds__(256)
void gemm_qkv_kernel(const float* __restrict__ x,
                     const float* __restrict__ Wq, const float* __restrict__ bq,
                     const float* __restrict__ Wk, const float* __restrict__ bk,
                     const float* __restrict__ Wv, const float* __restrict__ bv)
{
    const int mode = blockIdx.z;
    const float* W    = (mode == 0) ? Wq : (mode == 1) ? Wk : Wv;
    const float* bias = (mode == 0) ? bq : (mode == 1) ? bk : bv;
    gemm_body(x, W, bias, nullptr, mode, blockIdx.y, blockIdx.x);
}

// Output projection.
__global__ __launch_bounds__(256)
void gemm_o_kernel(const float* __restrict__ Wo, const float* __restrict__ bo,
                   float* __restrict__ out)
{
    gemm_body(g_att, Wo, bo, out, 3, blockIdx.y, blockIdx.x);
}

// ---------------------------------------------------------------------------
// Register-tiled causal flash attention, 8x8 micro-tile,
// cp.async double-buffered K/V staging (one barrier per tile).
// Block 128 thr: tx 0..7 (8 keys / 8 dk-cols each), ty 0..15 (8 q rows each).
// (unchanged from R14 — passing at 1784 us)
// ---------------------------------------------------------------------------
#define QS_STRIDE 128        // floats
#define KS_STRIDE 64         // floats
#define KS_SZ     (64 * KS_STRIDE)   // floats per K/V stage
#define PP_STRIDE 17         // u64
#define PCHUNK    16
#define SMEM_Q   (64 * QS_STRIDE * 4)   // 32768
#define SMEM_K   (2 * KS_SZ * 4)        // 32768
#define SMEM_V   (2 * KS_SZ * 4)        // 32768
#define SMEM_P   (64 * PP_STRIDE * 8)   // 8704
#define SMEM_ATTN (SMEM_Q + SMEM_K + SMEM_V + SMEM_P)   // 107008

__global__ __launch_bounds__(128)
void attn_kernel()
{
    extern __shared__ char smraw[];
    float* Qs = (float*)smraw;                           // [64 dk][128]
    float* Ks = (float*)(smraw + SMEM_Q);                // [2][64 dk][64 key]
    float* Vs = (float*)(smraw + SMEM_Q + SMEM_K);       // [2][64 key][64 dk]
    u64*   Pp = (u64*)(smraw + SMEM_Q + SMEM_K + SMEM_V);// [64 rowpair][17]

    const int tid = threadIdx.x;
    const int tx  = tid & 7;
    const int ty  = tid >> 3;
    const int qt  = (SS / QT - 1) - blockIdx.x;   // heaviest first
    const int h   = blockIdx.y;
    const int b   = blockIdx.z;

    const size_t ho_t = (size_t)(b * HH + h) * DK * SS;   // Qt/Kt base
    const size_t ho_v = (size_t)(b * HH + h) * SS * DK;   // V base

    const int srow = tid >> 4;       // staging row 0..7 base
    const int sg4  = tid & 15;       // staging float4 group

    // ---- prefetch K/V tile 0 via cp.async ----
    #pragma unroll
    for (int u = 0; u < 8; u++) {
        const int row = u * 8 + srow;
        cp16(&Ks[row * KS_STRIDE + sg4 * 4],
             g_Kt + ho_t + (size_t)row * SS + sg4 * 4);
        cp16(&Vs[row * KS_STRIDE + sg4 * 4],
             g_V + ho_v + (size_t)row * DK + sg4 * 4);
    }
    CP_COMMIT();

    // ---- stage Q tile (overlaps with the in-flight cp.async group) ----
    #pragma unroll
    for (int u = 0; u < 16; u++) {
        const int idx = u * 128 + tid;
        const int dk  = idx >> 5;
        const int rg  = idx & 31;
        float4 v = *(const float4*)(g_Qt + ho_t + (size_t)dk * SS + qt * QT + rg * 4);
        *(float4*)&Qs[dk * QS_STRIDE + rg * 4] = v;
    }

    u64 acc2[4][8];
    #pragma unroll
    for (int i = 0; i < 4; i++)
        #pragma unroll
        for (int j = 0; j < 8; j++) acc2[i][j] = 0ull;

    float m[8], l[8];
    #pragma unroll
    for (int r = 0; r < 8; r++) { m[r] = -1e30f; l[r] = 0.f; }

    const float scale = 0.125f;   // 1/sqrt(64)
    const int ntiles = 2 * qt + 2;

    CP_WAIT0();
    __syncthreads();

    for (int kt = 0; kt < ntiles; kt++) {
        // ---- prefetch next K/V tile into the other buffer ----
        if (kt + 1 < ntiles) {
            const int nb = (kt + 1) & 1;
            const size_t kcol = (size_t)(kt + 1) * KT;
            #pragma unroll
            for (int u = 0; u < 8; u++) {
                const int row = u * 8 + srow;
                cp16(&Ks[nb * KS_SZ + row * KS_STRIDE + sg4 * 4],
                     g_Kt + ho_t + (size_t)row * SS + kcol + sg4 * 4);
                cp16(&Vs[nb * KS_SZ + row * KS_STRIDE + sg4 * 4],
                     g_V + ho_v + (kcol + row) * DK + sg4 * 4);
            }
            CP_COMMIT();
        }

        const float* Kbuf = Ks + (kt & 1) * KS_SZ;
        const float* Vbuf = Vs + (kt & 1) * KS_SZ;

        // ---- QK^T: 8x8 score micro-tile ----
        u64 s2[4][8];
        #pragma unroll
        for (int i = 0; i < 4; i++)
            #pragma unroll
            for (int j = 0; j < 8; j++) s2[i][j] = 0ull;

        const float* QsT = Qs + ty * 8;
        const float* KsT = Kbuf + tx * 8;
        #pragma unroll 4
        for (int dk = 0; dk < 64; dk++) {
            ulonglong2 qlo = *(const ulonglong2*)(QsT + dk * QS_STRIDE);
            ulonglong2 qhi = *(const ulonglong2*)(QsT + dk * QS_STRIDE + 4);
            float4 ka = *(const float4*)(KsT + dk * KS_STRIDE);
            float4 kb = *(const float4*)(KsT + dk * KS_STRIDE + 4);
            const u64 k0 = pack2(ka.x), k1 = pack2(ka.y), k2 = pack2(ka.z), k3 = pack2(ka.w);
            const u64 k4 = pack2(kb.x), k5 = pack2(kb.y), k6 = pack2(kb.z), k7 = pack2(kb.w);
            s2[0][0] = ffma2(qlo.x, k0, s2[0][0]);  s2[0][1] = ffma2(qlo.x, k1, s2[0][1]);
            s2[0][2] = ffma2(qlo.x, k2, s2[0][2]);  s2[0][3] = ffma2(qlo.x, k3, s2[0][3]);
            s2[0][4] = ffma2(qlo.x, k4, s2[0][4]);  s2[0][5] = ffma2(qlo.x, k5, s2[0][5]);
            s2[0][6] = ffma2(qlo.x, k6, s2[0][6]);  s2[0][7] = ffma2(qlo.x, k7, s2[0][7]);
            s2[1][0] = ffma2(qlo.y, k0, s2[1][0]);  s2[1][1] = ffma2(qlo.y, k1, s2[1][1]);
            s2[1][2] = ffma2(qlo.y, k2, s2[1][2]);  s2[1][3] = ffma2(qlo.y, k3, s2[1][3]);
            s2[1][4] = ffma2(qlo.y, k4, s2[1][4]);  s2[1][5] = ffma2(qlo.y, k5, s2[1][5]);
            s2[1][6] = ffma2(qlo.y, k6, s2[1][6]);  s2[1][7] = ffma2(qlo.y, k7, s2[1][7]);
            s2[2][0] = ffma2(qhi.x, k0, s2[2][0]);  s2[2][1] = ffma2(qhi.x, k1, s2[2][1]);
            s2[2][2] = ffma2(qhi.x, k2, s2[2][2]);  s2[2][3] = ffma2(qhi.x, k3, s2[2][3]);
            s2[2][4] = ffma2(qhi.x, k4, s2[2][4]);  s2[2][5] = ffma2(qhi.x, k5, s2[2][5]);
            s2[2][6] = ffma2(qhi.x, k6, s2[2][6]);  s2[2][7] = ffma2(qhi.x, k7, s2[2][7]);
            s2[3][0] = ffma2(qhi.y, k0, s2[3][0]);  s2[3][1] = ffma2(qhi.y, k1, s2[3][1]);
            s2[3][2] = ffma2(qhi.y, k2, s2[3][2]);  s2[3][3] = ffma2(qhi.y, k3, s2[3][3]);
            s2[3][4] = ffma2(qhi.y, k4, s2[3][4]);  s2[3][5] = ffma2(qhi.y, k5, s2[3][5]);
            s2[3][6] = ffma2(qhi.y, k6, s2[3][6]);  s2[3][7] = ffma2(qhi.y, k7, s2[3][7]);
        }

        // ---- unpack scores, scale, causal mask ----
        float p[8][8];
        #pragma unroll
        for (int rp = 0; rp < 4; rp++)
            #pragma unroll
            for (int c = 0; c < 8; c++) {
                float2 v = unpack2(s2[rp][c]);
                p[2 * rp][c]     = v.x * scale;
                p[2 * rp + 1][c] = v.y * scale;
            }

        if (kt >= 2 * qt) {   // diagonal tiles only
            const int rbase = qt * QT + ty * 8 - kt * KT;
            #pragma unroll
            for (int r = 0; r < 8; r++) {
                const int lim = rbase + r;
                #pragma unroll
                for (int c = 0; c < 8; c++)
                    if (tx * 8 + c > lim) p[r][c] = -1e30f;
            }
        }

        // ---- online softmax (row reductions over 8 tx lanes) ----
        float cc[8];
        #pragma unroll
        for (int r = 0; r < 8; r++) {
            float mx = fmaxf(fmaxf(fmaxf(p[r][0], p[r][1]), fmaxf(p[r][2], p[r][3])),
                             fmaxf(fmaxf(p[r][4], p[r][5]), fmaxf(p[r][6], p[r][7])));
            mx = fmaxf(mx, __shfl_xor_sync(0xffffffffu, mx, 1, 8));
            mx = fmaxf(mx, __shfl_xor_sync(0xffffffffu, mx, 2, 8));
            mx = fmaxf(mx, __shfl_xor_sync(0xffffffffu, mx, 4, 8));
            const float mn = fmaxf(m[r], mx);
            cc[r] = __expf(m[r] - mn);
            l[r] *= cc[r];
            m[r] = mn;
        }
        #pragma unroll
        for (int rp = 0; rp < 4; rp++) {
            const u64 ccp = packpair(cc[2 * rp], cc[2 * rp + 1]);
            #pragma unroll
            for (int c = 0; c < 8; c++) acc2[rp][c] = fmul2(acc2[rp][c], ccp);
        }
        #pragma unroll
        for (int r = 0; r < 8; r++) {
            #pragma unroll
            for (int c = 0; c < 8; c++) p[r][c] = __expf(p[r][c] - m[r]);
            float rs = ((p[r][0] + p[r][1]) + (p[r][2] + p[r][3]))
                     + ((p[r][4] + p[r][5]) + (p[r][6] + p[r][7]));
            rs += __shfl_xor_sync(0xffffffffu, rs, 1, 8);
            rs += __shfl_xor_sync(0xffffffffu, rs, 2, 8);
            rs += __shfl_xor_sync(0xffffffffu, rs, 4, 8);
            l[r] += rs;
        }

        // ---- PV in 4 chunks of 16 keys through the small P buffer ----
        const float* VsT = Vbuf + tx * 8;
        const u64*   PpT = Pp + (ty * 4) * PP_STRIDE;
        const int    mych = tx >> 1;
        const int    col0 = (tx & 1) * 8;

        #pragma unroll
        for (int ch = 0; ch < 4; ch++) {
            if (mych == ch) {
                #pragma unroll
                for (int rp = 0; rp < 4; rp++) {
                    u64* dst = Pp + (ty * 4 + rp) * PP_STRIDE + col0;
                    #pragma unroll
                    for (int c = 0; c < 8; c++)
                        dst[c] = packpair(p[2 * rp][c], p[2 * rp + 1][c]);
                }
            }
            __syncwarp();

            #pragma unroll 2
            for (int j = 0; j < PCHUNK; j++) {
                const int jj = ch * PCHUNK + j;
                const u64 pA = PpT[j];
                const u64 pB = PpT[PP_STRIDE + j];
                const u64 pC = PpT[2 * PP_STRIDE + j];
                const u64 pD = PpT[3 * PP_STRIDE + j];
                float4 va = *(const float4*)(VsT + jj * KS_STRIDE);
                float4 vb = *(const float4*)(VsT + jj * KS_STRIDE + 4);
                const u64 v0 = pack2(va.x), v1 = pack2(va.y), v2 = pack2(va.z), v3 = pack2(va.w);
                const u64 v4 = pack2(vb.x), v5 = pack2(vb.y), v6 = pack2(vb.z), v7 = pack2(vb.w);
                acc2[0][0] = ffma2(pA, v0, acc2[0][0]);  acc2[0][1] = ffma2(pA, v1, acc2[0][1]);
                acc2[0][2] = ffma2(pA, v2, acc2[0][2]);  acc2[0][3] = ffma2(pA, v3, acc2[0][3]);
                acc2[0][4] = ffma2(pA, v4, acc2[0][4]);  acc2[0][5] = ffma2(pA, v5, acc2[0][5]);
                acc2[0][6] = ffma2(pA, v6, acc2[0][6]);  acc2[0][7] = ffma2(pA, v7, acc2[0][7]);
                acc2[1][0] = ffma2(pB, v0, acc2[1][0]);  acc2[1][1] = ffma2(pB, v1, acc2[1][1]);
                acc2[1][2] = ffma2(pB, v2, acc2[1][2]);  acc2[1][3] = ffma2(pB, v3, acc2[1][3]);
                acc2[1][4] = ffma2(pB, v4, acc2[1][4]);  acc2[1][5] = ffma2(pB, v5, acc2[1][5]);
                acc2[1][6] = ffma2(pB, v6, acc2[1][6]);  acc2[1][7] = ffma2(pB, v7, acc2[1][7]);
                acc2[2][0] = ffma2(pC, v0, acc2[2][0]);  acc2[2][1] = ffma2(pC, v1, acc2[2][1]);
                acc2[2][2] = ffma2(pC, v2, acc2[2][2]);  acc2[2][3] = ffma2(pC, v3, acc2[2][3]);
                acc2[2][4] = ffma2(pC, v4, acc2[2][4]);  acc2[2][5] = ffma2(pC, v5, acc2[2][5]);
                acc2[2][6] = ffma2(pC, v6, acc2[2][6]);  acc2[2][7] = ffma2(pC, v7, acc2[2][7]);
                acc2[3][0] = ffma2(pD, v0, acc2[3][0]);  acc2[3][1] = ffma2(pD, v1, acc2[3][1]);
                acc2[3][2] = ffma2(pD, v2, acc2[3][2]);  acc2[3][3] = ffma2(pD, v3, acc2[3][3]);
                acc2[3][4] = ffma2(pD, v4, acc2[3][4]);  acc2[3][5] = ffma2(pD, v5, acc2[3][5]);
                acc2[3][6] = ffma2(pD, v6, acc2[3][6]);  acc2[3][7] = ffma2(pD, v7, acc2[3][7]);
            }
            __syncwarp();
        }

        // ---- wait for next tile's fills; one barrier per tile ----
        CP_WAIT0();
        __syncthreads();
    }

    // ---- epilogue: normalize and write ----
    #pragma unroll
    for (int rp = 0; rp < 4; rp++) {
        const float inv0 = 1.f / l[2 * rp];
        const float inv1 = 1.f / l[2 * rp + 1];
        float o0[8], o1[8];
        #pragma unroll
        for (int c = 0; c < 8; c++) {
            float2 v = unpack2(acc2[rp][c]);
            o0[c] = v.x * inv0;
            o1[c] = v.y * inv1;
        }
        const size_t row0 = (size_t)(b * SS + qt * QT + ty * 8 + 2 * rp);
        float* dst0 = g_att + row0 * DD + h * DK + tx * 8;
        *(float4*)dst0            = make_float4(o0[0], o0[1], o0[2], o0[3]);
        *(float4*)(dst0 + 4)      = make_float4(o0[4], o0[5], o0[6], o0[7]);
        *(float4*)(dst0 + DD)     = make_float4(o1[0], o1[1], o1[2], o1[3]);
        *(float4*)(dst0 + DD + 4) = make_float4(o1[4], o1[5], o1[6], o1[7]);
    }
}

// ---------------------------------------------------------------------------
// Launch
// ---------------------------------------------------------------------------
extern "C" void kernel_launch(void* const* d_in, const int* in_sizes, int n_in,
                              void* d_out, int out_size)
{
    const float* x  = (const float*)d_in[0];
    const float* Wq = (const float*)d_in[1];
    const float* bq = (const float*)d_in[2];
    const float* Wk = (const float*)d_in[3];
    const float* bk = (const float*)d_in[4];
    const float* Wv = (const float*)d_in[5];
    const float* bv = (const float*)d_in[6];
    const float* Wo = (const float*)d_in[7];
    const float* bo = (const float*)d_in[8];
    float* out = (float*)d_out;

    dim3 qkv_grid(DD / 128, MM / 128, 3);   // (4, 64, 3)
    gemm_qkv_kernel<<<qkv_grid, 256>>>(x, Wq, bq, Wk, bk, Wv, bv);

    cudaFuncSetAttribute(attn_kernel,
                         cudaFuncAttributeMaxDynamicSharedMemorySize,
                         SMEM_ATTN);
    attn_kernel<<<dim3(SS / QT, HH, BB), 128, SMEM_ATTN>>>();

    dim3 o_grid(DD / 128, MM / 128);        // (4, 64)
    gemm_o_kernel<<<o_grid, 256>>>(Wo, bo, out);
}

// round 17
// speedup vs baseline: 1.2791x; 1.0522x over previous
#include <cuda_runtime.h>

// Problem constants
#define BB 2
#define SS 4096
#define DD 512
#define HH 8
#define DK 64
#define MM (BB * SS)   // 8192 rows
#define QT 128         // q rows per attention block
#define KT 64          // k cols per attention tile

// ---------------------------------------------------------------------------
// Scratch (device globals — no runtime allocation)
// ---------------------------------------------------------------------------
__device__ __align__(16) float g_Qt[BB * HH * DK * SS];
__device__ __align__(16) float g_Kt[BB * HH * DK * SS];
__device__ __align__(16) float g_V [BB * HH * SS * DK];
__device__ __align__(16) float g_att[BB * SS * DD];       // [B,S,D]

// ---------------------------------------------------------------------------
// Packed fp32x2 + cp.async helpers
// ---------------------------------------------------------------------------
typedef unsigned long long u64;
typedef unsigned int u32;

__device__ __forceinline__ u64 ffma2(u64 a, u64 b, u64 c) {
    u64 d;
    asm("fma.rn.f32x2 %0, %1, %2, %3;" : "=l"(d) : "l"(a), "l"(b), "l"(c));
    return d;
}
__device__ __forceinline__ u64 fmul2(u64 a, u64 b) {
    u64 d;
    asm("mul.rn.f32x2 %0, %1, %2;" : "=l"(d) : "l"(a), "l"(b));
    return d;
}
__device__ __forceinline__ u64 pack2(float x) {
    u64 d;
    asm("mov.b64 %0, {%1, %1};" : "=l"(d) : "f"(x));
    return d;
}
__device__ __forceinline__ u64 packpair(float a, float b) {
    u64 d;
    asm("mov.b64 %0, {%1, %2};" : "=l"(d) : "f"(a), "f"(b));
    return d;
}
__device__ __forceinline__ float2 unpack2(u64 v) {
    float2 r;
    asm("mov.b64 {%0, %1}, %2;" : "=f"(r.x), "=f"(r.y) : "l"(v));
    return r;
}
__device__ __forceinline__ void cp16(void* smem_dst, const void* gmem_src) {
    u32 s = (u32)__cvta_generic_to_shared(smem_dst);
    asm volatile("cp.async.cg.shared.global [%0], [%1], 16;" :: "r"(s), "l"(gmem_src));
}
#define CP_COMMIT() asm volatile("cp.async.commit_group;")
#define CP_WAIT0()  asm volatile("cp.async.wait_group 0;")

// ---------------------------------------------------------------------------
// GEMM body, 128x128 block tile, 8x8 micro-tile, software-pipelined k-loop.
//   As[k][row]: broadcast u64 row-pairs. Bs[k][col]: 2 LDS.128.
//   k+1 operands loaded into registers BEFORE the FFMA2 block of k.
// ---------------------------------------------------------------------------
__device__ __forceinline__
void gemm_body(const float* __restrict__ Ap,
               const float* __restrict__ W,
               const float* __restrict__ bias,
               float* __restrict__ Cout,
               int mode, int bm, int bn)
{
    __shared__ __align__(16) float As[16][128];
    __shared__ __align__(16) float Bs[16][128];

    const int tid = threadIdx.x;
    const int tx  = tid & 15;
    const int ty  = tid >> 4;

    const int lrow = tid >> 1;         // 0..127
    const int lk8  = (tid & 1) << 3;   // 0 or 8

    const float* Aptr = Ap + (size_t)(bm * 128 + lrow) * DD + lk8;
    const float* Wptr = W  + (size_t)(bn * 128 + lrow) * DD + lk8;

    u64 acc[4][8];
    #pragma unroll
    for (int i = 0; i < 4; i++)
        #pragma unroll
        for (int j = 0; j < 8; j++) acc[i][j] = 0ull;

    float4 a0 = *(const float4*)(Aptr);
    float4 a1 = *(const float4*)(Aptr + 4);
    float4 w0 = *(const float4*)(Wptr);
    float4 w1 = *(const float4*)(Wptr + 4);

    const float* AsT = &As[0][ty << 3];
    const float* BsT = &Bs[0][tx << 3];

    for (int kk = 0; kk < DD; kk += 16) {
        __syncthreads();
        As[lk8 + 0][lrow] = a0.x;  As[lk8 + 1][lrow] = a0.y;
        As[lk8 + 2][lrow] = a0.z;  As[lk8 + 3][lrow] = a0.w;
        As[lk8 + 4][lrow] = a1.x;  As[lk8 + 5][lrow] = a1.y;
        As[lk8 + 6][lrow] = a1.z;  As[lk8 + 7][lrow] = a1.w;
        Bs[lk8 + 0][lrow] = w0.x;  Bs[lk8 + 1][lrow] = w0.y;
        Bs[lk8 + 2][lrow] = w0.z;  Bs[lk8 + 3][lrow] = w0.w;
        Bs[lk8 + 4][lrow] = w1.x;  Bs[lk8 + 5][lrow] = w1.y;
        Bs[lk8 + 6][lrow] = w1.z;  Bs[lk8 + 7][lrow] = w1.w;

        if (kk + 16 < DD) {
            a0 = *(const float4*)(Aptr + kk + 16);
            a1 = *(const float4*)(Aptr + kk + 20);
            w0 = *(const float4*)(Wptr + kk + 16);
            w1 = *(const float4*)(Wptr + kk + 20);
        }
        __syncthreads();

        // --- software-pipelined 16-step k-loop ---
        ulonglong2 nA0 = *(const ulonglong2*)(AsT);
        ulonglong2 nA1 = *(const ulonglong2*)(AsT + 4);
        float4 nb03 = *(const float4*)(BsT);
        float4 nb47 = *(const float4*)(BsT + 4);

        #pragma unroll
        for (int k = 0; k < 16; k++) {
            const ulonglong2 A0 = nA0, A1 = nA1;
            const float4 b03 = nb03, b47 = nb47;
            if (k < 15) {
                nA0  = *(const ulonglong2*)(AsT + (k + 1) * 128);
                nA1  = *(const ulonglong2*)(AsT + (k + 1) * 128 + 4);
                nb03 = *(const float4*)(BsT + (k + 1) * 128);
                nb47 = *(const float4*)(BsT + (k + 1) * 128 + 4);
            }
            const u64 ra = A0.x, rb = A0.y, rc = A1.x, rd = A1.y;
            const u64 c0 = pack2(b03.x), c1 = pack2(b03.y);
            const u64 c2 = pack2(b03.z), c3 = pack2(b03.w);
            const u64 c4 = pack2(b47.x), c5 = pack2(b47.y);
            const u64 c6 = pack2(b47.z), c7 = pack2(b47.w);
            acc[0][0] = ffma2(ra, c0, acc[0][0]);  acc[0][1] = ffma2(ra, c1, acc[0][1]);
            acc[0][2] = ffma2(ra, c2, acc[0][2]);  acc[0][3] = ffma2(ra, c3, acc[0][3]);
            acc[0][4] = ffma2(ra, c4, acc[0][4]);  acc[0][5] = ffma2(ra, c5, acc[0][5]);
            acc[0][6] = ffma2(ra, c6, acc[0][6]);  acc[0][7] = ffma2(ra, c7, acc[0][7]);
            acc[1][0] = ffma2(rb, c0, acc[1][0]);  acc[1][1] = ffma2(rb, c1, acc[1][1]);
            acc[1][2] = ffma2(rb, c2, acc[1][2]);  acc[1][3] = ffma2(rb, c3, acc[1][3]);
            acc[1][4] = ffma2(rb, c4, acc[1][4]);  acc[1][5] = ffma2(rb, c5, acc[1][5]);
            acc[1][6] = ffma2(rb, c6, acc[1][6]);  acc[1][7] = ffma2(rb, c7, acc[1][7]);
            acc[2][0] = ffma2(rc, c0, acc[2][0]);  acc[2][1] = ffma2(rc, c1, acc[2][1]);
            acc[2][2] = ffma2(rc, c2, acc[2][2]);  acc[2][3] = ffma2(rc, c3, acc[2][3]);
            acc[2][4] = ffma2(rc, c4, acc[2][4]);  acc[2][5] = ffma2(rc, c5, acc[2][5]);
            acc[2][6] = ffma2(rc, c6, acc[2][6]);  acc[2][7] = ffma2(rc, c7, acc[2][7]);
            acc[3][0] = ffma2(rd, c0, acc[3][0]);  acc[3][1] = ffma2(rd, c1, acc[3][1]);
            acc[3][2] = ffma2(rd, c2, acc[3][2]);  acc[3][3] = ffma2(rd, c3, acc[3][3]);
            acc[3][4] = ffma2(rd, c4, acc[3][4]);  acc[3][5] = ffma2(rd, c5, acc[3][5]);
            acc[3][6] = ffma2(rd, c6, acc[3][6]);  acc[3][7] = ffma2(rd, c7, acc[3][7]);
        }
    }

    // ---- epilogue ----
    const int r00 = bm * 128 + (ty << 3);
    const int c0  = bn * 128 + (tx << 3);

    float bi[8];
    {
        float4 b03 = *(const float4*)&bias[c0];
        float4 b47 = *(const float4*)&bias[c0 + 4];
        bi[0] = b03.x; bi[1] = b03.y; bi[2] = b03.z; bi[3] = b03.w;
        bi[4] = b47.x; bi[5] = b47.y; bi[6] = b47.z; bi[7] = b47.w;
    }

    const int b_  = r00 >> 12;
    const int s00 = r00 & 4095;
    const int h   = c0 >> 6;
    const int dk0 = c0 & 63;

    #pragma unroll
    for (int rp = 0; rp < 4; rp++) {
        float o0[8], o1[8];
        #pragma unroll
        for (int c = 0; c < 8; c++) {
            float2 v = unpack2(acc[rp][c]);
            o0[c] = v.x + bi[c];
            o1[c] = v.y + bi[c];
        }
        if (mode < 2) {
            float* qkv = (mode == 0) ? g_Qt : g_Kt;
            float* hb = &qkv[((size_t)(b_ * HH + h) * DK + dk0) * SS];
            const int s0 = s00 + 2 * rp;
            #pragma unroll
            for (int c = 0; c < 8; c++) {
                float* base = &hb[(size_t)c * SS + s0];
                base[0] = o0[c];
                base[1] = o1[c];
            }
        } else if (mode == 2) {
            const int s0 = s00 + 2 * rp;
            float* dst0 = &g_V[(((size_t)(b_ * HH + h) << 12) + s0) * DK + dk0];
            *(float4*)dst0            = make_float4(o0[0], o0[1], o0[2], o0[3]);
            *(float4*)(dst0 + 4)      = make_float4(o0[4], o0[5], o0[6], o0[7]);
            *(float4*)(dst0 + DK)     = make_float4(o1[0], o1[1], o1[2], o1[3]);
            *(float4*)(dst0 + DK + 4) = make_float4(o1[4], o1[5], o1[6], o1[7]);
        } else {
            const int row0 = r00 + 2 * rp;
            float* dst0 = &Cout[(size_t)row0 * DD + c0];
            *(float4*)dst0            = make_float4(o0[0], o0[1], o0[2], o0[3]);
            *(float4*)(dst0 + 4)      = make_float4(o0[4], o0[5], o0[6], o0[7]);
            *(float4*)(dst0 + DD)     = make_float4(o1[0], o1[1], o1[2], o1[3]);
            *(float4*)(dst0 + DD + 4) = make_float4(o1[4], o1[5], o1[6], o1[7]);
        }
    }
}

__global__ __launch_bounds__(256, 2)
void gemm_qkv_kernel(const float* __restrict__ x,
                     const float* __restrict__ Wq, const float* __restrict__ bq,
                     const float* __restrict__ Wk, const float* __restrict__ bk,
                     const float* __restrict__ Wv, const float* __restrict__ bv)
{
    const int mode = blockIdx.z;
    const float* W    = (mode == 0) ? Wq : (mode == 1) ? Wk : Wv;
    const float* bias = (mode == 0) ? bq : (mode == 1) ? bk : bv;
    gemm_body(x, W, bias, nullptr, mode, blockIdx.y, blockIdx.x);
}

__global__ __launch_bounds__(256, 2)
void gemm_o_kernel(const float* __restrict__ Wo, const float* __restrict__ bo,
                   float* __restrict__ out)
{
    gemm_body(g_att, Wo, bo, out, 3, blockIdx.y, blockIdx.x);
}

// ---------------------------------------------------------------------------
// Register-tiled causal flash attention, 8x8 micro-tile,
// cp.async double-buffered K/V staging, software-pipelined QK and PV loops.
// ---------------------------------------------------------------------------
#define QS_STRIDE 128        // floats
#define KS_STRIDE 64         // floats
#define KS_SZ     (64 * KS_STRIDE)   // floats per K/V stage
#define PP_STRIDE 17         // u64
#define PCHUNK    16
#define SMEM_Q   (64 * QS_STRIDE * 4)   // 32768
#define SMEM_K   (2 * KS_SZ * 4)        // 32768
#define SMEM_V   (2 * KS_SZ * 4)        // 32768
#define SMEM_P   (64 * PP_STRIDE * 8)   // 8704
#define SMEM_ATTN (SMEM_Q + SMEM_K + SMEM_V + SMEM_P)   // 107008

__global__ __launch_bounds__(128)
void attn_kernel()
{
    extern __shared__ char smraw[];
    float* Qs = (float*)smraw;                           // [64 dk][128]
    float* Ks = (float*)(smraw + SMEM_Q);                // [2][64 dk][64 key]
    float* Vs = (float*)(smraw + SMEM_Q + SMEM_K);       // [2][64 key][64 dk]
    u64*   Pp = (u64*)(smraw + SMEM_Q + SMEM_K + SMEM_V);// [64 rowpair][17]

    const int tid = threadIdx.x;
    const int tx  = tid & 7;
    const int ty  = tid >> 3;
    const int qt  = (SS / QT - 1) - blockIdx.x;   // heaviest first
    const int h   = blockIdx.y;
    const int b   = blockIdx.z;

    const size_t ho_t = (size_t)(b * HH + h) * DK * SS;
    const size_t ho_v = (size_t)(b * HH + h) * SS * DK;

    const int srow = tid >> 4;
    const int sg4  = tid & 15;

    // ---- prefetch K/V tile 0 via cp.async ----
    #pragma unroll
    for (int u = 0; u < 8; u++) {
        const int row = u * 8 + srow;
        cp16(&Ks[row * KS_STRIDE + sg4 * 4],
             g_Kt + ho_t + (size_t)row * SS + sg4 * 4);
        cp16(&Vs[row * KS_STRIDE + sg4 * 4],
             g_V + ho_v + (size_t)row * DK + sg4 * 4);
    }
    CP_COMMIT();

    // ---- stage Q tile ----
    #pragma unroll
    for (int u = 0; u < 16; u++) {
        const int idx = u * 128 + tid;
        const int dk  = idx >> 5;
        const int rg  = idx & 31;
        float4 v = *(const float4*)(g_Qt + ho_t + (size_t)dk * SS + qt * QT + rg * 4);
        *(float4*)&Qs[dk * QS_STRIDE + rg * 4] = v;
    }

    u64 acc2[4][8];
    #pragma unroll
    for (int i = 0; i < 4; i++)
        #pragma unroll
        for (int j = 0; j < 8; j++) acc2[i][j] = 0ull;

    float m[8], l[8];
    #pragma unroll
    for (int r = 0; r < 8; r++) { m[r] = -1e30f; l[r] = 0.f; }

    const float scale = 0.125f;
    const int ntiles = 2 * qt + 2;

    CP_WAIT0();
    __syncthreads();

    for (int kt = 0; kt < ntiles; kt++) {
        if (kt + 1 < ntiles) {
            const int nb = (kt + 1) & 1;
            const size_t kcol = (size_t)(kt + 1) * KT;
            #pragma unroll
            for (int u = 0; u < 8; u++) {
                const int row = u * 8 + srow;
                cp16(&Ks[nb * KS_SZ + row * KS_STRIDE + sg4 * 4],
                     g_Kt + ho_t + (size_t)row * SS + kcol + sg4 * 4);
                cp16(&Vs[nb * KS_SZ + row * KS_STRIDE + sg4 * 4],
                     g_V + ho_v + (kcol + row) * DK + sg4 * 4);
            }
            CP_COMMIT();
        }

        const float* Kbuf = Ks + (kt & 1) * KS_SZ;
        const float* Vbuf = Vs + (kt & 1) * KS_SZ;

        // ---- QK^T: software-pipelined dk-loop ----
        u64 s2[4][8];
        #pragma unroll
        for (int i = 0; i < 4; i++)
            #pragma unroll
            for (int j = 0; j < 8; j++) s2[i][j] = 0ull;

        const float* QsT = Qs + ty * 8;
        const float* KsT = Kbuf + tx * 8;

        ulonglong2 nqlo = *(const ulonglong2*)(QsT);
        ulonglong2 nqhi = *(const ulonglong2*)(QsT + 4);
        float4 nka = *(const float4*)(KsT);
        float4 nkb = *(const float4*)(KsT + 4);

        #pragma unroll 4
        for (int dk = 0; dk < 64; dk++) {
            const ulonglong2 qlo = nqlo, qhi = nqhi;
            const float4 ka = nka, kb = nkb;
            if (dk < 63) {
                nqlo = *(const ulonglong2*)(QsT + (dk + 1) * QS_STRIDE);
                nqhi = *(const ulonglong2*)(QsT + (dk + 1) * QS_STRIDE + 4);
                nka  = *(const float4*)(KsT + (dk + 1) * KS_STRIDE);
                nkb  = *(const float4*)(KsT + (dk + 1) * KS_STRIDE + 4);
            }
            const u64 k0 = pack2(ka.x), k1 = pack2(ka.y), k2 = pack2(ka.z), k3 = pack2(ka.w);
            const u64 k4 = pack2(kb.x), k5 = pack2(kb.y), k6 = pack2(kb.z), k7 = pack2(kb.w);
            s2[0][0] = ffma2(qlo.x, k0, s2[0][0]);  s2[0][1] = ffma2(qlo.x, k1, s2[0][1]);
            s2[0][2] = ffma2(qlo.x, k2, s2[0][2]);  s2[0][3] = ffma2(qlo.x, k3, s2[0][3]);
            s2[0][4] = ffma2(qlo.x, k4, s2[0][4]);  s2[0][5] = ffma2(qlo.x, k5, s2[0][5]);
            s2[0][6] = ffma2(qlo.x, k6, s2[0][6]);  s2[0][7] = ffma2(qlo.x, k7, s2[0][7]);
            s2[1][0] = ffma2(qlo.y, k0, s2[1][0]);  s2[1][1] = ffma2(qlo.y, k1, s2[1][1]);
            s2[1][2] = ffma2(qlo.y, k2, s2[1][2]);  s2[1][3] = ffma2(qlo.y, k3, s2[1][3]);
            s2[1][4] = ffma2(qlo.y, k4, s2[1][4]);  s2[1][5] = ffma2(qlo.y, k5, s2[1][5]);
            s2[1][6] = ffma2(qlo.y, k6, s2[1][6]);  s2[1][7] = ffma2(qlo.y, k7, s2[1][7]);
            s2[2][0] = ffma2(qhi.x, k0, s2[2][0]);  s2[2][1] = ffma2(qhi.x, k1, s2[2][1]);
            s2[2][2] = ffma2(qhi.x, k2, s2[2][2]);  s2[2][3] = ffma2(qhi.x, k3, s2[2][3]);
            s2[2][4] = ffma2(qhi.x, k4, s2[2][4]);  s2[2][5] = ffma2(qhi.x, k5, s2[2][5]);
            s2[2][6] = ffma2(qhi.x, k6, s2[2][6]);  s2[2][7] = ffma2(qhi.x, k7, s2[2][7]);
            s2[3][0] = ffma2(qhi.y, k0, s2[3][0]);  s2[3][1] = ffma2(qhi.y, k1, s2[3][1]);
            s2[3][2] = ffma2(qhi.y, k2, s2[3][2]);  s2[3][3] = ffma2(qhi.y, k3, s2[3][3]);
            s2[3][4] = ffma2(qhi.y, k4, s2[3][4]);  s2[3][5] = ffma2(qhi.y, k5, s2[3][5]);
            s2[3][6] = ffma2(qhi.y, k6, s2[3][6]);  s2[3][7] = ffma2(qhi.y, k7, s2[3][7]);
        }

        // ---- unpack scores, scale, causal mask ----
        float p[8][8];
        #pragma unroll
        for (int rp = 0; rp < 4; rp++)
            #pragma unroll
            for (int c = 0; c < 8; c++) {
                float2 v = unpack2(s2[rp][c]);
                p[2 * rp][c]     = v.x * scale;
                p[2 * rp + 1][c] = v.y * scale;
            }

        if (kt >= 2 * qt) {
            const int rbase = qt * QT + ty * 8 - kt * KT;
            #pragma unroll
            for (int r = 0; r < 8; r++) {
                const int lim = rbase + r;
                #pragma unroll
                for (int c = 0; c < 8; c++)
                    if (tx * 8 + c > lim) p[r][c] = -1e30f;
            }
        }

        // ---- online softmax ----
        float cc[8];
        #pragma unroll
        for (int r = 0; r < 8; r++) {
            float mx = fmaxf(fmaxf(fmaxf(p[r][0], p[r][1]), fmaxf(p[r][2], p[r][3])),
                             fmaxf(fmaxf(p[r][4], p[r][5]), fmaxf(p[r][6], p[r][7])));
            mx = fmaxf(mx, __shfl_xor_sync(0xffffffffu, mx, 1, 8));
            mx = fmaxf(mx, __shfl_xor_sync(0xffffffffu, mx, 2, 8));
            mx = fmaxf(mx, __shfl_xor_sync(0xffffffffu, mx, 4, 8));
            const float mn = fmaxf(m[r], mx);
            cc[r] = __expf(m[r] - mn);
            l[r] *= cc[r];
            m[r] = mn;
        }
        #pragma unroll
        for (int rp = 0; rp < 4; rp++) {
            const u64 ccp = packpair(cc[2 * rp], cc[2 * rp + 1]);
            #pragma unroll
            for (int c = 0; c < 8; c++) acc2[rp][c] = fmul2(acc2[rp][c], ccp);
        }
        #pragma unroll
        for (int r = 0; r < 8; r++) {
            #pragma unroll
            for (int c = 0; c < 8; c++) p[r][c] = __expf(p[r][c] - m[r]);
            float rs = ((p[r][0] + p[r][1]) + (p[r][2] + p[r][3]))
                     + ((p[r][4] + p[r][5]) + (p[r][6] + p[r][7]));
            rs += __shfl_xor_sync(0xffffffffu, rs, 1, 8);
            rs += __shfl_xor_sync(0xffffffffu, rs, 2, 8);
            rs += __shfl_xor_sync(0xffffffffu, rs, 4, 8);
            l[r] += rs;
        }

        // ---- PV in 4 chunks of 16 keys, software-pipelined j-loop ----
        const float* VsT = Vbuf + tx * 8;
        const u64*   PpT = Pp + (ty * 4) * PP_STRIDE;
        const int    mych = tx >> 1;
        const int    col0 = (tx & 1) * 8;

        #pragma unroll
        for (int ch = 0; ch < 4; ch++) {
            if (mych == ch) {
                #pragma unroll
                for (int rp = 0; rp < 4; rp++) {
                    u64* dst = Pp + (ty * 4 + rp) * PP_STRIDE + col0;
                    #pragma unroll
                    for (int c = 0; c < 8; c++)
                        dst[c] = packpair(p[2 * rp][c], p[2 * rp + 1][c]);
                }
            }
            __syncwarp();

            const int jj0 = ch * PCHUNK;
            u64 npA = PpT[0];
            u64 npB = PpT[PP_STRIDE];
            u64 npC = PpT[2 * PP_STRIDE];
            u64 npD = PpT[3 * PP_STRIDE];
            float4 nva = *(const float4*)(VsT + jj0 * KS_STRIDE);
            float4 nvb = *(const float4*)(VsT + jj0 * KS_STRIDE + 4);

            #pragma unroll 4
            for (int j = 0; j < PCHUNK; j++) {
                const u64 pA = npA, pB = npB, pC = npC, pD = npD;
                const float4 va = nva, vb = nvb;
                if (j < PCHUNK - 1) {
                    npA = PpT[j + 1];
                    npB = PpT[PP_STRIDE + j + 1];
                    npC = PpT[2 * PP_STRIDE + j + 1];
                    npD = PpT[3 * PP_STRIDE + j + 1];
                    nva = *(const float4*)(VsT + (jj0 + j + 1) * KS_STRIDE);
                    nvb = *(const float4*)(VsT + (jj0 + j + 1) * KS_STRIDE + 4);
                }
                const u64 v0 = pack2(va.x), v1 = pack2(va.y), v2 = pack2(va.z), v3 = pack2(va.w);
                const u64 v4 = pack2(vb.x), v5 = pack2(vb.y), v6 = pack2(vb.z), v7 = pack2(vb.w);
                acc2[0][0] = ffma2(pA, v0, acc2[0][0]);  acc2[0][1] = ffma2(pA, v1, acc2[0][1]);
                acc2[0][2] = ffma2(pA, v2, acc2[0][2]);  acc2[0][3] = ffma2(pA, v3, acc2[0][3]);
                acc2[0][4] = ffma2(pA, v4, acc2[0][4]);  acc2[0][5] = ffma2(pA, v5, acc2[0][5]);
                acc2[0][6] = ffma2(pA, v6, acc2[0][6]);  acc2[0][7] = ffma2(pA, v7, acc2[0][7]);
                acc2[1][0] = ffma2(pB, v0, acc2[1][0]);  acc2[1][1] = ffma2(pB, v1, acc2[1][1]);
                acc2[1][2] = ffma2(pB, v2, acc2[1][2]);  acc2[1][3] = ffma2(pB, v3, acc2[1][3]);
                acc2[1][4] = ffma2(pB, v4, acc2[1][4]);  acc2[1][5] = ffma2(pB, v5, acc2[1][5]);
                acc2[1][6] = ffma2(pB, v6, acc2[1][6]);  acc2[1][7] = ffma2(pB, v7, acc2[1][7]);
                acc2[2][0] = ffma2(pC, v0, acc2[2][0]);  acc2[2][1] = ffma2(pC, v1, acc2[2][1]);
                acc2[2][2] = ffma2(pC, v2, acc2[2][2]);  acc2[2][3] = ffma2(pC, v3, acc2[2][3]);
                acc2[2][4] = ffma2(pC, v4, acc2[2][4]);  acc2[2][5] = ffma2(pC, v5, acc2[2][5]);
                acc2[2][6] = ffma2(pC, v6, acc2[2][6]);  acc2[2][7] = ffma2(pC, v7, acc2[2][7]);
                acc2[3][0] = ffma2(pD, v0, acc2[3][0]);  acc2[3][1] = ffma2(pD, v1, acc2[3][1]);
                acc2[3][2] = ffma2(pD, v2, acc2[3][2]);  acc2[3][3] = ffma2(pD, v3, acc2[3][3]);
                acc2[3][4] = ffma2(pD, v4, acc2[3][4]);  acc2[3][5] = ffma2(pD, v5, acc2[3][5]);
                acc2[3][6] = ffma2(pD, v6, acc2[3][6]);  acc2[3][7] = ffma2(pD, v7, acc2[3][7]);
            }
            __syncwarp();
        }

        CP_WAIT0();
        __syncthreads();
    }

    // ---- epilogue: normalize and write ----
    #pragma unroll
    for (int rp = 0; rp < 4; rp++) {
        const float inv0 = 1.f / l[2 * rp];
        const float inv1 = 1.f / l[2 * rp + 1];
        float o0[8], o1[8];
        #pragma unroll
        for (int c = 0; c < 8; c++) {
            float2 v = unpack2(acc2[rp][c]);
            o0[c] = v.x * inv0;
            o1[c] = v.y * inv1;
        }
        const size_t row0 = (size_t)(b * SS + qt * QT + ty * 8 + 2 * rp);
        float* dst0 = g_att + row0 * DD + h * DK + tx * 8;
        *(float4*)dst0            = make_float4(o0[0], o0[1], o0[2], o0[3]);
        *(float4*)(dst0 + 4)      = make_float4(o0[4], o0[5], o0[6], o0[7]);
        *(float4*)(dst0 + DD)     = make_float4(o1[0], o1[1], o1[2], o1[3]);
        *(float4*)(dst0 + DD + 4) = make_float4(o1[4], o1[5], o1[6], o1[7]);
    }
}

// ---------------------------------------------------------------------------
// Launch
// ---------------------------------------------------------------------------
extern "C" void kernel_launch(void* const* d_in, const int* in_sizes, int n_in,
                              void* d_out, int out_size)
{
    const float* x  = (const float*)d_in[0];
    const float* Wq = (const float*)d_in[1];
    const float* bq = (const float*)d_in[2];
    const float* Wk = (const float*)d_in[3];
    const float* bk = (const float*)d_in[4];
    const float* Wv = (const float*)d_in[5];
    const float* bv = (const float*)d_in[6];
    const float* Wo = (const float*)d_in[7];
    const float* bo = (const float*)d_in[8];
    float* out = (float*)d_out;

    dim3 qkv_grid(DD / 128, MM / 128, 3);   // (4, 64, 3)
    gemm_qkv_kernel<<<qkv_grid, 256>>>(x, Wq, bq, Wk, bk, Wv, bv);

    cudaFuncSetAttribute(attn_kernel,
                         cudaFuncAttributeMaxDynamicSharedMemorySize,
                         SMEM_ATTN);
    attn_kernel<<<dim3(SS / QT, HH, BB), 128, SMEM_ATTN>>>();

    dim3 o_grid(DD / 128, MM / 128);        // (4, 64)
    gemm_o_kernel<<<o_grid, 256>>>(Wo, bo, out);
}